// round 2
// baseline (speedup 1.0000x reference)
#include <cuda_runtime.h>
#include <cstdint>

#define NQ      16384
#define NKV     32768
#define DEC     64
#define NF      128
#define NBATCH  8
#define NQB     2048   // q rows per batch
#define NKB     4096   // kv rows per batch
#define BN_EPS  1e-4f

// ---------------- scratch (alloc-free: device globals) ----------------
__device__ float g_xdec[NQ * NF];
__device__ float g_q   [NQ * NF];
__device__ float g_k   [NKV * NF];
__device__ float g_v   [NKV * NF];
__device__ float g_xr  [NQ * NF];
__device__ float g_t   [NQ * NF];
__device__ float g_psum[(NQ / 64) * NF];
__device__ float g_psq [(NQ / 64) * NF];
__device__ float g_mean[NF];
__device__ float g_rstd[NF];

// ======================================================================
// Kernel 1: x_dec = einsum('nkc,kcf->nf', x_dec_feat[nbr], W_p1)
// Tiled gathered GEMM: BM=64, BN=128 (full nf), 27 segments of K=64.
// 256 threads = 16x16, each computes a 4x8 microtile.
// ======================================================================
__global__ void k_p1(const float* __restrict__ xf, const int* __restrict__ nbr,
                     const float* __restrict__ Wp1)
{
    extern __shared__ float sm[];
    float* As = sm;              // [64 c][68]  (c-major, transposed)
    float* Bs = sm + 64 * 68;    // [64 c][128 n]

    const int tid = threadIdx.x;
    const int tx = tid & 15, ty = tid >> 4;
    const int m0 = blockIdx.x * 64;

    float acc[4][8];
#pragma unroll
    for (int i = 0; i < 4; ++i)
#pragma unroll
        for (int j = 0; j < 8; ++j) acc[i][j] = 0.f;

    for (int k = 0; k < 27; ++k) {
        __syncthreads();
        // gather A: 64 rows x 64 cols, transposed store
#pragma unroll
        for (int i = 0; i < 4; ++i) {
            int idx = tid + i * 256;        // 0..1023
            int r   = idx >> 4;             // 0..63
            int c4  = idx & 15;             // 0..15
            int g   = nbr[(m0 + r) * 27 + k];
            float4 v = *reinterpret_cast<const float4*>(xf + (size_t)g * DEC + c4 * 4);
            As[(c4 * 4 + 0) * 68 + r] = v.x;
            As[(c4 * 4 + 1) * 68 + r] = v.y;
            As[(c4 * 4 + 2) * 68 + r] = v.z;
            As[(c4 * 4 + 3) * 68 + r] = v.w;
        }
        const float* Bk = Wp1 + (size_t)k * 64 * 128;
#pragma unroll
        for (int i = 0; i < 8; ++i) {
            int idx = tid + i * 256;        // 0..2047
            int r   = idx >> 5;
            int c4  = idx & 31;
            *reinterpret_cast<float4*>(Bs + r * 128 + c4 * 4) =
                *reinterpret_cast<const float4*>(Bk + r * 128 + c4 * 4);
        }
        __syncthreads();
#pragma unroll 16
        for (int c = 0; c < 64; ++c) {
            float4 a  = *reinterpret_cast<const float4*>(As + c * 68 + ty * 4);
            float4 b0 = *reinterpret_cast<const float4*>(Bs + c * 128 + tx * 8);
            float4 b1 = *reinterpret_cast<const float4*>(Bs + c * 128 + tx * 8 + 4);
            float av[4] = {a.x, a.y, a.z, a.w};
            float bv[8] = {b0.x, b0.y, b0.z, b0.w, b1.x, b1.y, b1.z, b1.w};
#pragma unroll
            for (int i = 0; i < 4; ++i)
#pragma unroll
                for (int j = 0; j < 8; ++j) acc[i][j] += av[i] * bv[j];
        }
    }
#pragma unroll
    for (int i = 0; i < 4; ++i) {
        float* o = g_xdec + (size_t)(m0 + ty * 4 + i) * 128 + tx * 8;
        float4 v0 = {acc[i][0], acc[i][1], acc[i][2], acc[i][3]};
        float4 v1 = {acc[i][4], acc[i][5], acc[i][6], acc[i][7]};
        *reinterpret_cast<float4*>(o)     = v0;
        *reinterpret_cast<float4*>(o + 4) = v1;
    }
}

// ======================================================================
// Generic tiled GEMM: C[M,128] = A[M,KA] @ B[KA,128].  BM=64, BK=64.
// STATS: also emit per-block column sum / sumsq partials (deterministic).
// ======================================================================
template <int KA, bool STATS>
__global__ void k_gemm(const float* __restrict__ A, const float* __restrict__ Bm,
                       float* __restrict__ C)
{
    extern __shared__ float sm[];
    float* As = sm;              // [64][68] transposed
    float* Bs = sm + 64 * 68;    // [64][128]

    const int tid = threadIdx.x;
    const int tx = tid & 15, ty = tid >> 4;
    const int m0 = blockIdx.x * 64;

    float acc[4][8];
#pragma unroll
    for (int i = 0; i < 4; ++i)
#pragma unroll
        for (int j = 0; j < 8; ++j) acc[i][j] = 0.f;

    for (int kb = 0; kb < KA; kb += 64) {
        __syncthreads();
#pragma unroll
        for (int i = 0; i < 4; ++i) {
            int idx = tid + i * 256;
            int r   = idx >> 4;
            int c4  = idx & 15;
            float4 v = *reinterpret_cast<const float4*>(A + (size_t)(m0 + r) * KA + kb + c4 * 4);
            As[(c4 * 4 + 0) * 68 + r] = v.x;
            As[(c4 * 4 + 1) * 68 + r] = v.y;
            As[(c4 * 4 + 2) * 68 + r] = v.z;
            As[(c4 * 4 + 3) * 68 + r] = v.w;
        }
#pragma unroll
        for (int i = 0; i < 8; ++i) {
            int idx = tid + i * 256;
            int r   = idx >> 5;
            int c4  = idx & 31;
            *reinterpret_cast<float4*>(Bs + r * 128 + c4 * 4) =
                *reinterpret_cast<const float4*>(Bm + (size_t)(kb + r) * 128 + c4 * 4);
        }
        __syncthreads();
#pragma unroll 16
        for (int c = 0; c < 64; ++c) {
            float4 a  = *reinterpret_cast<const float4*>(As + c * 68 + ty * 4);
            float4 b0 = *reinterpret_cast<const float4*>(Bs + c * 128 + tx * 8);
            float4 b1 = *reinterpret_cast<const float4*>(Bs + c * 128 + tx * 8 + 4);
            float av[4] = {a.x, a.y, a.z, a.w};
            float bv[8] = {b0.x, b0.y, b0.z, b0.w, b1.x, b1.y, b1.z, b1.w};
#pragma unroll
            for (int i = 0; i < 4; ++i)
#pragma unroll
                for (int j = 0; j < 8; ++j) acc[i][j] += av[i] * bv[j];
        }
    }
#pragma unroll
    for (int i = 0; i < 4; ++i) {
        float* o = C + (size_t)(m0 + ty * 4 + i) * 128 + tx * 8;
        float4 v0 = {acc[i][0], acc[i][1], acc[i][2], acc[i][3]};
        float4 v1 = {acc[i][4], acc[i][5], acc[i][6], acc[i][7]};
        *reinterpret_cast<float4*>(o)     = v0;
        *reinterpret_cast<float4*>(o + 4) = v1;
    }

    if (STATS) {
        // deterministic per-block column sums of C and C^2 (reuse smem)
        float* rsum = sm;              // [16][128]
        float* rsq  = sm + 16 * 128;   // [16][128]
        __syncthreads();
#pragma unroll
        for (int j = 0; j < 8; ++j) {
            float s = 0.f, q = 0.f;
#pragma unroll
            for (int i = 0; i < 4; ++i) { float v = acc[i][j]; s += v; q += v * v; }
            rsum[ty * 128 + tx * 8 + j] = s;
            rsq [ty * 128 + tx * 8 + j] = q;
        }
        __syncthreads();
        if (tid < 128) {
            float s = 0.f, q = 0.f;
#pragma unroll
            for (int t = 0; t < 16; ++t) { s += rsum[t * 128 + tid]; q += rsq[t * 128 + tid]; }
            g_psum[blockIdx.x * 128 + tid] = s;
            g_psq [blockIdx.x * 128 + tid] = q;
        }
    }
}

// ======================================================================
// Kernel: flash attention (fp32, no 1/sqrt(d) scale).
// Block: 64 q-rows, full d=128.  Loops kv in tiles of 64. 256 threads.
// grid = (32 q-tiles, 8 batches)
// ======================================================================
__global__ void k_attn()
{
    extern __shared__ float sm[];
    float* Qt = sm;                      // [128 d][68]  transposed
    float* Kt = Qt + 128 * 68;           // [128 d][68]  transposed
    float* Vs = Kt + 128 * 68;           // [64 j][128 n]
    float* Pt = Vs + 64 * 128;           // [64 j][68 i] transposed

    const int tid = threadIdx.x;
    const int tx = tid & 15, ty = tid >> 4;
    const int b = blockIdx.y, qt = blockIdx.x;

    const float* Q = g_q + ((size_t)b * NQB + qt * 64) * 128;
#pragma unroll
    for (int i = 0; i < 8; ++i) {
        int idx = tid + i * 256;            // 0..2047
        int r   = idx >> 5;                 // 0..63
        int c4  = idx & 31;                 // 0..31
        float4 v = *reinterpret_cast<const float4*>(Q + r * 128 + c4 * 4);
        Qt[(c4 * 4 + 0) * 68 + r] = v.x;
        Qt[(c4 * 4 + 1) * 68 + r] = v.y;
        Qt[(c4 * 4 + 2) * 68 + r] = v.z;
        Qt[(c4 * 4 + 3) * 68 + r] = v.w;
    }

    float O[4][8];
#pragma unroll
    for (int i = 0; i < 4; ++i)
#pragma unroll
        for (int j = 0; j < 8; ++j) O[i][j] = 0.f;
    float mr[4] = {-1e30f, -1e30f, -1e30f, -1e30f};
    float lr[4] = {0.f, 0.f, 0.f, 0.f};

    for (int jt = 0; jt < NKB / 64; ++jt) {
        const float* K = g_k + ((size_t)b * NKB + jt * 64) * 128;
        const float* V = g_v + ((size_t)b * NKB + jt * 64) * 128;
        __syncthreads();
#pragma unroll
        for (int i = 0; i < 8; ++i) {
            int idx = tid + i * 256;
            int r   = idx >> 5;
            int c4  = idx & 31;
            float4 kv = *reinterpret_cast<const float4*>(K + r * 128 + c4 * 4);
            Kt[(c4 * 4 + 0) * 68 + r] = kv.x;
            Kt[(c4 * 4 + 1) * 68 + r] = kv.y;
            Kt[(c4 * 4 + 2) * 68 + r] = kv.z;
            Kt[(c4 * 4 + 3) * 68 + r] = kv.w;
            *reinterpret_cast<float4*>(Vs + r * 128 + c4 * 4) =
                *reinterpret_cast<const float4*>(V + r * 128 + c4 * 4);
        }
        __syncthreads();

        // S = Q Kt : 4x4 microtile per thread
        float s[4][4];
#pragma unroll
        for (int i = 0; i < 4; ++i)
#pragma unroll
            for (int j = 0; j < 4; ++j) s[i][j] = 0.f;
#pragma unroll 8
        for (int d = 0; d < 128; ++d) {
            float4 qv = *reinterpret_cast<const float4*>(Qt + d * 68 + ty * 4);
            float4 kv = *reinterpret_cast<const float4*>(Kt + d * 68 + tx * 4);
            float qa[4] = {qv.x, qv.y, qv.z, qv.w};
            float ka[4] = {kv.x, kv.y, kv.z, kv.w};
#pragma unroll
            for (int i = 0; i < 4; ++i)
#pragma unroll
                for (int j = 0; j < 4; ++j) s[i][j] += qa[i] * ka[j];
        }

        // online softmax per row (rows i owned by 16-lane tx-groups)
        float sc[4];
#pragma unroll
        for (int i = 0; i < 4; ++i) {
            float rm = fmaxf(fmaxf(s[i][0], s[i][1]), fmaxf(s[i][2], s[i][3]));
#pragma unroll
            for (int off = 1; off < 16; off <<= 1)
                rm = fmaxf(rm, __shfl_xor_sync(0xffffffffu, rm, off));
            float mnew = fmaxf(mr[i], rm);
            float p0 = __expf(s[i][0] - mnew);
            float p1 = __expf(s[i][1] - mnew);
            float p2 = __expf(s[i][2] - mnew);
            float p3 = __expf(s[i][3] - mnew);
            float rs = (p0 + p1) + (p2 + p3);
#pragma unroll
            for (int off = 1; off < 16; off <<= 1)
                rs += __shfl_xor_sync(0xffffffffu, rs, off);
            float scale = __expf(mr[i] - mnew);
            lr[i] = lr[i] * scale + rs;
            mr[i] = mnew;
            sc[i] = scale;
            Pt[(tx * 4 + 0) * 68 + ty * 4 + i] = p0;
            Pt[(tx * 4 + 1) * 68 + ty * 4 + i] = p1;
            Pt[(tx * 4 + 2) * 68 + ty * 4 + i] = p2;
            Pt[(tx * 4 + 3) * 68 + ty * 4 + i] = p3;
        }
#pragma unroll
        for (int i = 0; i < 4; ++i)
#pragma unroll
            for (int n = 0; n < 8; ++n) O[i][n] *= sc[i];
        __syncthreads();

        // O += P @ V
#pragma unroll 8
        for (int j = 0; j < 64; ++j) {
            float4 pv = *reinterpret_cast<const float4*>(Pt + j * 68 + ty * 4);
            float4 v0 = *reinterpret_cast<const float4*>(Vs + j * 128 + tx * 8);
            float4 v1 = *reinterpret_cast<const float4*>(Vs + j * 128 + tx * 8 + 4);
            float pa[4] = {pv.x, pv.y, pv.z, pv.w};
            float va[8] = {v0.x, v0.y, v0.z, v0.w, v1.x, v1.y, v1.z, v1.w};
#pragma unroll
            for (int i = 0; i < 4; ++i)
#pragma unroll
                for (int n = 0; n < 8; ++n) O[i][n] += pa[i] * va[n];
        }
    }

    float* XR = g_xr + ((size_t)b * NQB + qt * 64) * 128;
#pragma unroll
    for (int i = 0; i < 4; ++i) {
        float inv = 1.f / lr[i];
        float* o = XR + (size_t)(ty * 4 + i) * 128 + tx * 8;
        float4 v0 = {O[i][0] * inv, O[i][1] * inv, O[i][2] * inv, O[i][3] * inv};
        float4 v1 = {O[i][4] * inv, O[i][5] * inv, O[i][6] * inv, O[i][7] * inv};
        *reinterpret_cast<float4*>(o)     = v0;
        *reinterpret_cast<float4*>(o + 4) = v1;
    }
}

// ======================================================================
// BN stats finalize: sum 256 partials (deterministic order)
// ======================================================================
__global__ void k_stats()
{
    int f = threadIdx.x;   // 0..127
    float s = 0.f, q = 0.f;
    for (int b = 0; b < NQ / 64; ++b) {
        s += g_psum[b * 128 + f];
        q += g_psq [b * 128 + f];
    }
    float mean = s * (1.f / NQ);
    float var  = q * (1.f / NQ) - mean * mean;
    g_mean[f] = mean;
    g_rstd[f] = rsqrtf(var + BN_EPS);
}

// ======================================================================
// Epilogue: out = x_dec + (t - mean) * rstd * gamma + beta
// ======================================================================
__global__ void k_final(const float* __restrict__ gamma, const float* __restrict__ beta,
                        float* __restrict__ out)
{
    int idx = blockIdx.x * 256 + threadIdx.x;       // float4 index
    int f   = (idx & 31) * 4;
    float4 t  = *reinterpret_cast<const float4*>(g_t    + (size_t)idx * 4);
    float4 xd = *reinterpret_cast<const float4*>(g_xdec + (size_t)idx * 4);
    float4 r;
    r.x = xd.x + (t.x - g_mean[f + 0]) * g_rstd[f + 0] * gamma[f + 0] + beta[f + 0];
    r.y = xd.y + (t.y - g_mean[f + 1]) * g_rstd[f + 1] * gamma[f + 1] + beta[f + 1];
    r.z = xd.z + (t.z - g_mean[f + 2]) * g_rstd[f + 2] * gamma[f + 2] + beta[f + 2];
    r.w = xd.w + (t.w - g_mean[f + 3]) * g_rstd[f + 3] * gamma[f + 3] + beta[f + 3];
    *reinterpret_cast<float4*>(out + (size_t)idx * 4) = r;
}

// ======================================================================
extern "C" void kernel_launch(void* const* d_in, const int* in_sizes, int n_in,
                              void* d_out, int out_size)
{
    const float* xdec_f = (const float*)d_in[0];
    const float* xenc_f = (const float*)d_in[1];
    const int*   nbr    = (const int*)  d_in[2];
    const float* Wp1    = (const float*)d_in[3];
    const float* Wq     = (const float*)d_in[4];
    const float* Wk     = (const float*)d_in[5];
    const float* Wv     = (const float*)d_in[6];
    const float* Wt     = (const float*)d_in[7];
    const float* gamma  = (const float*)d_in[8];
    const float* beta   = (const float*)d_in[9];
    float* out = (float*)d_out;

    float *p_xdec, *p_q, *p_k, *p_v, *p_xr, *p_t;
    cudaGetSymbolAddress((void**)&p_xdec, g_xdec);
    cudaGetSymbolAddress((void**)&p_q,    g_q);
    cudaGetSymbolAddress((void**)&p_k,    g_k);
    cudaGetSymbolAddress((void**)&p_v,    g_v);
    cudaGetSymbolAddress((void**)&p_xr,   g_xr);
    cudaGetSymbolAddress((void**)&p_t,    g_t);

    const int GSM = (64 * 68 + 64 * 128) * 4;                       // 50176 B
    const int ASM = (2 * 128 * 68 + 64 * 128 + 64 * 68) * 4;        // 119808 B
    cudaFuncSetAttribute(k_p1,              cudaFuncAttributeMaxDynamicSharedMemorySize, GSM);
    cudaFuncSetAttribute(k_gemm<64,  false>, cudaFuncAttributeMaxDynamicSharedMemorySize, GSM);
    cudaFuncSetAttribute(k_gemm<128, false>, cudaFuncAttributeMaxDynamicSharedMemorySize, GSM);
    cudaFuncSetAttribute(k_gemm<128, true>,  cudaFuncAttributeMaxDynamicSharedMemorySize, GSM);
    cudaFuncSetAttribute(k_attn,            cudaFuncAttributeMaxDynamicSharedMemorySize, ASM);

    k_p1<<<NQ / 64, 256, GSM>>>(xdec_f, nbr, Wp1);
    k_gemm<64,  false><<<NKV / 64, 256, GSM>>>(xenc_f, Wk, p_k);
    k_gemm<64,  false><<<NKV / 64, 256, GSM>>>(xenc_f, Wv, p_v);
    k_gemm<128, false><<<NQ  / 64, 256, GSM>>>(p_xdec, Wq, p_q);
    k_attn<<<dim3(NQB / 64, NBATCH), 256, ASM>>>();
    k_gemm<128, true ><<<NQ  / 64, 256, GSM>>>(p_xr, Wt, p_t);
    k_stats<<<1, 128>>>();
    k_final<<<(NQ * NF / 4) / 256, 256>>>(gamma, beta, out);
}

// round 3
// speedup vs baseline: 2.2894x; 2.2894x over previous
#include <cuda_runtime.h>
#include <cuda_bf16.h>
#include <cstdint>

#define NQ      16384
#define NKV     32768
#define DEC     64
#define NF      128
#define NBATCH  8
#define NQB     2048
#define NKB     4096
#define BN_EPS  1e-4f

// ---------------- scratch (alloc-free: device globals) ----------------
__device__ float g_xdec[NQ * NF];
__device__ float g_xr  [NQ * NF];
__device__ float g_t   [NQ * NF];
__device__ float g_psum[(NQ / 64) * NF];
__device__ float g_psq [(NQ / 64) * NF];
__device__ float g_mean[NF];
__device__ float g_rstd[NF];
// split-bf16 operands for tensor-core attention
__device__ __nv_bfloat16 g_qh[NQ * NF],  g_ql[NQ * NF];
__device__ __nv_bfloat16 g_kh[NKV * NF], g_kl[NKV * NF];
__device__ __nv_bfloat16 g_vh[NKV * NF], g_vl[NKV * NF];

// ---------------- helpers ----------------
__device__ __forceinline__ uint32_t packb(__nv_bfloat16 x, __nv_bfloat16 y) {
    __nv_bfloat162 v(x, y);
    return *reinterpret_cast<uint32_t*>(&v);
}
__device__ __forceinline__ void split2(float a, float b, uint32_t& hi, uint32_t& lo) {
    __nv_bfloat16 ah = __float2bfloat16(a);
    __nv_bfloat16 bh = __float2bfloat16(b);
    float ar = a - __bfloat162float(ah);
    float br = b - __bfloat162float(bh);
    hi = packb(ah, bh);
    lo = packb(__float2bfloat16(ar), __float2bfloat16(br));
}
__device__ __forceinline__ void mma16816(float* d, const uint32_t* a, const uint32_t* b) {
    asm volatile("mma.sync.aligned.m16n8k16.row.col.f32.bf16.bf16.f32 "
                 "{%0,%1,%2,%3}, {%4,%5,%6,%7}, {%8,%9}, {%0,%1,%2,%3};"
                 : "+f"(d[0]), "+f"(d[1]), "+f"(d[2]), "+f"(d[3])
                 : "r"(a[0]), "r"(a[1]), "r"(a[2]), "r"(a[3]), "r"(b[0]), "r"(b[1]));
}
__device__ __forceinline__ void ldsm4(uint32_t* r, uint32_t addr) {
    asm volatile("ldmatrix.sync.aligned.m8n8.x4.shared.b16 {%0,%1,%2,%3}, [%4];"
                 : "=r"(r[0]), "=r"(r[1]), "=r"(r[2]), "=r"(r[3]) : "r"(addr));
}
__device__ __forceinline__ void ldsm4t(uint32_t* r, uint32_t addr) {
    asm volatile("ldmatrix.sync.aligned.m8n8.x4.trans.shared.b16 {%0,%1,%2,%3}, [%4];"
                 : "=r"(r[0]), "=r"(r[1]), "=r"(r[2]), "=r"(r[3]) : "r"(addr));
}

// ======================================================================
// Kernel 1: x_dec = einsum('nkc,kcf->nf', x_dec_feat[nbr], W_p1)  (fp32)
// ======================================================================
__global__ void k_p1(const float* __restrict__ xf, const int* __restrict__ nbr,
                     const float* __restrict__ Wp1)
{
    extern __shared__ float sm[];
    float* As = sm;
    float* Bs = sm + 64 * 68;

    const int tid = threadIdx.x;
    const int tx = tid & 15, ty = tid >> 4;
    const int m0 = blockIdx.x * 64;

    float acc[4][8];
#pragma unroll
    for (int i = 0; i < 4; ++i)
#pragma unroll
        for (int j = 0; j < 8; ++j) acc[i][j] = 0.f;

    for (int k = 0; k < 27; ++k) {
        __syncthreads();
#pragma unroll
        for (int i = 0; i < 4; ++i) {
            int idx = tid + i * 256;
            int r   = idx >> 4;
            int c4  = idx & 15;
            int g   = nbr[(m0 + r) * 27 + k];
            float4 v = *reinterpret_cast<const float4*>(xf + (size_t)g * DEC + c4 * 4);
            As[(c4 * 4 + 0) * 68 + r] = v.x;
            As[(c4 * 4 + 1) * 68 + r] = v.y;
            As[(c4 * 4 + 2) * 68 + r] = v.z;
            As[(c4 * 4 + 3) * 68 + r] = v.w;
        }
        const float* Bk = Wp1 + (size_t)k * 64 * 128;
#pragma unroll
        for (int i = 0; i < 8; ++i) {
            int idx = tid + i * 256;
            int r   = idx >> 5;
            int c4  = idx & 31;
            *reinterpret_cast<float4*>(Bs + r * 128 + c4 * 4) =
                *reinterpret_cast<const float4*>(Bk + r * 128 + c4 * 4);
        }
        __syncthreads();
#pragma unroll 16
        for (int c = 0; c < 64; ++c) {
            float4 a  = *reinterpret_cast<const float4*>(As + c * 68 + ty * 4);
            float4 b0 = *reinterpret_cast<const float4*>(Bs + c * 128 + tx * 8);
            float4 b1 = *reinterpret_cast<const float4*>(Bs + c * 128 + tx * 8 + 4);
            float av[4] = {a.x, a.y, a.z, a.w};
            float bv[8] = {b0.x, b0.y, b0.z, b0.w, b1.x, b1.y, b1.z, b1.w};
#pragma unroll
            for (int i = 0; i < 4; ++i)
#pragma unroll
                for (int j = 0; j < 8; ++j) acc[i][j] += av[i] * bv[j];
        }
    }
#pragma unroll
    for (int i = 0; i < 4; ++i) {
        float* o = g_xdec + (size_t)(m0 + ty * 4 + i) * 128 + tx * 8;
        float4 v0 = {acc[i][0], acc[i][1], acc[i][2], acc[i][3]};
        float4 v1 = {acc[i][4], acc[i][5], acc[i][6], acc[i][7]};
        *reinterpret_cast<float4*>(o)     = v0;
        *reinterpret_cast<float4*>(o + 4) = v1;
    }
}

// ======================================================================
// Tiled GEMM f32 out (+ optional BN stats partials)
// ======================================================================
template <int KA, bool STATS>
__global__ void k_gemm(const float* __restrict__ A, const float* __restrict__ Bm,
                       float* __restrict__ C)
{
    extern __shared__ float sm[];
    float* As = sm;
    float* Bs = sm + 64 * 68;

    const int tid = threadIdx.x;
    const int tx = tid & 15, ty = tid >> 4;
    const int m0 = blockIdx.x * 64;

    float acc[4][8];
#pragma unroll
    for (int i = 0; i < 4; ++i)
#pragma unroll
        for (int j = 0; j < 8; ++j) acc[i][j] = 0.f;

    for (int kb = 0; kb < KA; kb += 64) {
        __syncthreads();
#pragma unroll
        for (int i = 0; i < 4; ++i) {
            int idx = tid + i * 256;
            int r   = idx >> 4;
            int c4  = idx & 15;
            float4 v = *reinterpret_cast<const float4*>(A + (size_t)(m0 + r) * KA + kb + c4 * 4);
            As[(c4 * 4 + 0) * 68 + r] = v.x;
            As[(c4 * 4 + 1) * 68 + r] = v.y;
            As[(c4 * 4 + 2) * 68 + r] = v.z;
            As[(c4 * 4 + 3) * 68 + r] = v.w;
        }
#pragma unroll
        for (int i = 0; i < 8; ++i) {
            int idx = tid + i * 256;
            int r   = idx >> 5;
            int c4  = idx & 31;
            *reinterpret_cast<float4*>(Bs + r * 128 + c4 * 4) =
                *reinterpret_cast<const float4*>(Bm + (size_t)(kb + r) * 128 + c4 * 4);
        }
        __syncthreads();
#pragma unroll 16
        for (int c = 0; c < 64; ++c) {
            float4 a  = *reinterpret_cast<const float4*>(As + c * 68 + ty * 4);
            float4 b0 = *reinterpret_cast<const float4*>(Bs + c * 128 + tx * 8);
            float4 b1 = *reinterpret_cast<const float4*>(Bs + c * 128 + tx * 8 + 4);
            float av[4] = {a.x, a.y, a.z, a.w};
            float bv[8] = {b0.x, b0.y, b0.z, b0.w, b1.x, b1.y, b1.z, b1.w};
#pragma unroll
            for (int i = 0; i < 4; ++i)
#pragma unroll
                for (int j = 0; j < 8; ++j) acc[i][j] += av[i] * bv[j];
        }
    }
#pragma unroll
    for (int i = 0; i < 4; ++i) {
        float* o = C + (size_t)(m0 + ty * 4 + i) * 128 + tx * 8;
        float4 v0 = {acc[i][0], acc[i][1], acc[i][2], acc[i][3]};
        float4 v1 = {acc[i][4], acc[i][5], acc[i][6], acc[i][7]};
        *reinterpret_cast<float4*>(o)     = v0;
        *reinterpret_cast<float4*>(o + 4) = v1;
    }

    if (STATS) {
        float* rsum = sm;
        float* rsq  = sm + 16 * 128;
        __syncthreads();
#pragma unroll
        for (int j = 0; j < 8; ++j) {
            float s = 0.f, q = 0.f;
#pragma unroll
            for (int i = 0; i < 4; ++i) { float v = acc[i][j]; s += v; q += v * v; }
            rsum[ty * 128 + tx * 8 + j] = s;
            rsq [ty * 128 + tx * 8 + j] = q;
        }
        __syncthreads();
        if (tid < 128) {
            float s = 0.f, q = 0.f;
#pragma unroll
            for (int t = 0; t < 16; ++t) { s += rsum[t * 128 + tid]; q += rsq[t * 128 + tid]; }
            g_psum[blockIdx.x * 128 + tid] = s;
            g_psq [blockIdx.x * 128 + tid] = q;
        }
    }
}

// ======================================================================
// Tiled GEMM with split-bf16 (hi/lo) output epilogue
// ======================================================================
template <int KA>
__global__ void k_gemm_split(const float* __restrict__ A, const float* __restrict__ Bm,
                             __nv_bfloat16* __restrict__ Chi, __nv_bfloat16* __restrict__ Clo)
{
    extern __shared__ float sm[];
    float* As = sm;
    float* Bs = sm + 64 * 68;

    const int tid = threadIdx.x;
    const int tx = tid & 15, ty = tid >> 4;
    const int m0 = blockIdx.x * 64;

    float acc[4][8];
#pragma unroll
    for (int i = 0; i < 4; ++i)
#pragma unroll
        for (int j = 0; j < 8; ++j) acc[i][j] = 0.f;

    for (int kb = 0; kb < KA; kb += 64) {
        __syncthreads();
#pragma unroll
        for (int i = 0; i < 4; ++i) {
            int idx = tid + i * 256;
            int r   = idx >> 4;
            int c4  = idx & 15;
            float4 v = *reinterpret_cast<const float4*>(A + (size_t)(m0 + r) * KA + kb + c4 * 4);
            As[(c4 * 4 + 0) * 68 + r] = v.x;
            As[(c4 * 4 + 1) * 68 + r] = v.y;
            As[(c4 * 4 + 2) * 68 + r] = v.z;
            As[(c4 * 4 + 3) * 68 + r] = v.w;
        }
#pragma unroll
        for (int i = 0; i < 8; ++i) {
            int idx = tid + i * 256;
            int r   = idx >> 5;
            int c4  = idx & 31;
            *reinterpret_cast<float4*>(Bs + r * 128 + c4 * 4) =
                *reinterpret_cast<const float4*>(Bm + (size_t)(kb + r) * 128 + c4 * 4);
        }
        __syncthreads();
#pragma unroll 16
        for (int c = 0; c < 64; ++c) {
            float4 a  = *reinterpret_cast<const float4*>(As + c * 68 + ty * 4);
            float4 b0 = *reinterpret_cast<const float4*>(Bs + c * 128 + tx * 8);
            float4 b1 = *reinterpret_cast<const float4*>(Bs + c * 128 + tx * 8 + 4);
            float av[4] = {a.x, a.y, a.z, a.w};
            float bv[8] = {b0.x, b0.y, b0.z, b0.w, b1.x, b1.y, b1.z, b1.w};
#pragma unroll
            for (int i = 0; i < 4; ++i)
#pragma unroll
                for (int j = 0; j < 8; ++j) acc[i][j] += av[i] * bv[j];
        }
    }
#pragma unroll
    for (int i = 0; i < 4; ++i) {
        size_t off = (size_t)(m0 + ty * 4 + i) * 128 + tx * 8;
        uint32_t hv[4], lv[4];
#pragma unroll
        for (int jj = 0; jj < 4; ++jj)
            split2(acc[i][2 * jj], acc[i][2 * jj + 1], hv[jj], lv[jj]);
        uint4 uh = {hv[0], hv[1], hv[2], hv[3]};
        uint4 ul = {lv[0], lv[1], lv[2], lv[3]};
        *reinterpret_cast<uint4*>(Chi + off) = uh;
        *reinterpret_cast<uint4*>(Clo + off) = ul;
    }
}

// ======================================================================
// Flash attention with bf16-split tensor-core MMA.
// Block: 64 q-rows, 256 threads (8 warps = 4 qw x 2 kw). kv tile 64.
// grid = (32 q-tiles, 8 batches).
// ======================================================================
// smem byte offsets (bf16 tiles padded to 136 elems/row)
#define TB    (64 * 136 * 2)       // 17408 bytes per tile array
#define OKH   0
#define OKL   (TB)
#define OVH   (2 * TB)
#define OVL   (3 * TB)
#define OQH   (4 * TB)
#define OQL   (5 * TB)
#define OSTAT (6 * TB)             // 104448
#define ASMSZ (OSTAT + 256 * 4)    // 105472

__global__ __launch_bounds__(256) void k_attn()
{
    extern __shared__ char smr[];
    const uint32_t sbase = (uint32_t)__cvta_generic_to_shared(smr);
    float* sMax = reinterpret_cast<float*>(smr + OSTAT);          // [8][16]
    float* sSum = reinterpret_cast<float*>(smr + OSTAT + 512);    // [8][16]
    float* sOred = reinterpret_cast<float*>(smr);                 // reuse: [4][16][128]

    const int tid  = threadIdx.x;
    const int wid  = tid >> 5, lane = tid & 31;
    const int qw   = wid >> 1, kw = wid & 1;
    const int g    = lane >> 2, t = lane & 3;
    const int b    = blockIdx.y;
    const size_t qrow0 = (size_t)b * NQB + blockIdx.x * 64;

    // ldmatrix per-lane geometry
    const int rA = lane & 15;                 // A-frag row within tile
    const int cA = (lane >> 4) * 8;           // A-frag col offset
    const int rB = ((lane >> 3) & 2) * 4 + (lane & 7);   // K B-frag row
    const int cB = ((lane >> 3) & 1) * 8;                // K B-frag col off
    const int rV = ((lane >> 3) & 1) * 8 + (lane & 7);   // V trans row
    const int cV = ((lane >> 3) & 2) * 4;                // V trans col off

    // stage Q (hi/lo) for this block's 64 rows into smem
    {
        const __nv_bfloat16* qh = g_qh + qrow0 * 128;
        const __nv_bfloat16* ql = g_ql + qrow0 * 128;
        __nv_bfloat16* sqh = reinterpret_cast<__nv_bfloat16*>(smr + OQH);
        __nv_bfloat16* sql = reinterpret_cast<__nv_bfloat16*>(smr + OQL);
#pragma unroll
        for (int i = 0; i < 4; ++i) {
            int idx = tid + i * 256;
            int r = idx >> 4, c = idx & 15;
            *reinterpret_cast<uint4*>(sqh + r * 136 + c * 8) =
                *reinterpret_cast<const uint4*>(qh + (size_t)r * 128 + c * 8);
            *reinterpret_cast<uint4*>(sql + r * 136 + c * 8) =
                *reinterpret_cast<const uint4*>(ql + (size_t)r * 128 + c * 8);
        }
    }

    float O[16][4];
#pragma unroll
    for (int i = 0; i < 16; ++i)
#pragma unroll
        for (int j = 0; j < 4; ++j) O[i][j] = 0.f;
    float m0r = -1e30f, m1r = -1e30f, l0 = 0.f, l1 = 0.f;

    for (int jt = 0; jt < NKB / 64; ++jt) {
        __syncthreads();
        // stage K/V hi/lo tiles
        {
            size_t base = ((size_t)b * NKB + jt * 64) * 128;
            __nv_bfloat16* skh = reinterpret_cast<__nv_bfloat16*>(smr + OKH);
            __nv_bfloat16* skl = reinterpret_cast<__nv_bfloat16*>(smr + OKL);
            __nv_bfloat16* svh = reinterpret_cast<__nv_bfloat16*>(smr + OVH);
            __nv_bfloat16* svl = reinterpret_cast<__nv_bfloat16*>(smr + OVL);
#pragma unroll
            for (int i = 0; i < 4; ++i) {
                int idx = tid + i * 256;
                int r = idx >> 4, c = idx & 15;
                size_t go = base + (size_t)r * 128 + c * 8;
                int so = r * 136 + c * 8;
                *reinterpret_cast<uint4*>(skh + so) = *reinterpret_cast<const uint4*>(g_kh + go);
                *reinterpret_cast<uint4*>(skl + so) = *reinterpret_cast<const uint4*>(g_kl + go);
                *reinterpret_cast<uint4*>(svh + so) = *reinterpret_cast<const uint4*>(g_vh + go);
                *reinterpret_cast<uint4*>(svl + so) = *reinterpret_cast<const uint4*>(g_vl + go);
            }
        }
        __syncthreads();

        // ---- S = Q K^T  (split bf16: Qh*Kh + Qh*Kl + Ql*Kh) ----
        float sA[4][4];
#pragma unroll
        for (int i = 0; i < 4; ++i)
#pragma unroll
            for (int j = 0; j < 4; ++j) sA[i][j] = 0.f;

#pragma unroll
        for (int ch = 0; ch < 8; ++ch) {
            uint32_t Aaddr = sbase + (uint32_t)((qw * 16 + rA) * 136 + ch * 16 + cA) * 2;
            uint32_t Ah[4], Al[4];
            ldsm4(Ah, Aaddr + OQH);
            ldsm4(Al, Aaddr + OQL);

            uint32_t col = (uint32_t)(ch * 16 + cB) * 2;
            uint32_t a0 = sbase + (uint32_t)((kw * 32 + rB) * 136) * 2 + col;
            uint32_t a1 = sbase + (uint32_t)((kw * 32 + 16 + rB) * 136) * 2 + col;
            uint32_t bh0[4], bh1[4], bl0[4], bl1[4];
            ldsm4(bh0, a0 + OKH); ldsm4(bh1, a1 + OKH);
            ldsm4(bl0, a0 + OKL); ldsm4(bl1, a1 + OKL);

            mma16816(sA[0], Ah, bh0);     mma16816(sA[1], Ah, bh0 + 2);
            mma16816(sA[2], Ah, bh1);     mma16816(sA[3], Ah, bh1 + 2);
            mma16816(sA[0], Ah, bl0);     mma16816(sA[1], Ah, bl0 + 2);
            mma16816(sA[2], Ah, bl1);     mma16816(sA[3], Ah, bl1 + 2);
            mma16816(sA[0], Al, bh0);     mma16816(sA[1], Al, bh0 + 2);
            mma16816(sA[2], Al, bh1);     mma16816(sA[3], Al, bh1 + 2);
        }

        // ---- online softmax (rows g and g+8), pair exchange via smem ----
        float rm0 = sA[0][0], rm1 = sA[0][2];
#pragma unroll
        for (int nt = 0; nt < 4; ++nt) {
            rm0 = fmaxf(rm0, fmaxf(sA[nt][0], sA[nt][1]));
            rm1 = fmaxf(rm1, fmaxf(sA[nt][2], sA[nt][3]));
        }
        rm0 = fmaxf(rm0, __shfl_xor_sync(0xffffffffu, rm0, 1));
        rm0 = fmaxf(rm0, __shfl_xor_sync(0xffffffffu, rm0, 2));
        rm1 = fmaxf(rm1, __shfl_xor_sync(0xffffffffu, rm1, 1));
        rm1 = fmaxf(rm1, __shfl_xor_sync(0xffffffffu, rm1, 2));
        if (t == 0) {
            sMax[(qw * 2 + kw) * 16 + g]     = rm0;
            sMax[(qw * 2 + kw) * 16 + g + 8] = rm1;
        }
        asm volatile("bar.sync %0, %1;" :: "r"(qw + 1), "r"(64) : "memory");
        float om0 = sMax[(qw * 2 + (kw ^ 1)) * 16 + g];
        float om1 = sMax[(qw * 2 + (kw ^ 1)) * 16 + g + 8];
        float mn0 = fmaxf(m0r, fmaxf(rm0, om0));
        float mn1 = fmaxf(m1r, fmaxf(rm1, om1));
        float sc0 = __expf(m0r - mn0);
        float sc1 = __expf(m1r - mn1);

        float p[4][4];
        float ls0 = 0.f, ls1 = 0.f;
#pragma unroll
        for (int nt = 0; nt < 4; ++nt) {
            p[nt][0] = __expf(sA[nt][0] - mn0);
            p[nt][1] = __expf(sA[nt][1] - mn0);
            p[nt][2] = __expf(sA[nt][2] - mn1);
            p[nt][3] = __expf(sA[nt][3] - mn1);
            ls0 += p[nt][0] + p[nt][1];
            ls1 += p[nt][2] + p[nt][3];
        }
        ls0 += __shfl_xor_sync(0xffffffffu, ls0, 1);
        ls0 += __shfl_xor_sync(0xffffffffu, ls0, 2);
        ls1 += __shfl_xor_sync(0xffffffffu, ls1, 1);
        ls1 += __shfl_xor_sync(0xffffffffu, ls1, 2);
        if (t == 0) {
            sSum[(qw * 2 + kw) * 16 + g]     = ls0;
            sSum[(qw * 2 + kw) * 16 + g + 8] = ls1;
        }
        asm volatile("bar.sync %0, %1;" :: "r"(qw + 1), "r"(64) : "memory");
        float os0 = sSum[(qw * 2 + (kw ^ 1)) * 16 + g];
        float os1 = sSum[(qw * 2 + (kw ^ 1)) * 16 + g + 8];
        l0 = l0 * sc0 + ls0 + os0;
        l1 = l1 * sc1 + ls1 + os1;
        m0r = mn0; m1r = mn1;

#pragma unroll
        for (int nt = 0; nt < 16; ++nt) {
            O[nt][0] *= sc0; O[nt][1] *= sc0;
            O[nt][2] *= sc1; O[nt][3] *= sc1;
        }

        // ---- P fragments (split bf16), A-layout, from S accumulators ----
        uint32_t Ph[2][4], Pl[2][4];
#pragma unroll
        for (int c = 0; c < 2; ++c) {
            split2(p[2 * c][0],     p[2 * c][1],     Ph[c][0], Pl[c][0]);
            split2(p[2 * c][2],     p[2 * c][3],     Ph[c][1], Pl[c][1]);
            split2(p[2 * c + 1][0], p[2 * c + 1][1], Ph[c][2], Pl[c][2]);
            split2(p[2 * c + 1][2], p[2 * c + 1][3], Ph[c][3], Pl[c][3]);
        }

        // ---- O += P V  (Ph*Vh + Ph*Vl + Pl*Vh) ----
#pragma unroll
        for (int dp = 0; dp < 8; ++dp) {
            uint32_t col = (uint32_t)(dp * 16 + cV) * 2;
            uint32_t a0 = sbase + (uint32_t)((kw * 32 + rV) * 136) * 2 + col;
            uint32_t a1 = sbase + (uint32_t)((kw * 32 + 16 + rV) * 136) * 2 + col;
            uint32_t vh0[4], vh1[4], vl0[4], vl1[4];
            ldsm4t(vh0, a0 + OVH); ldsm4t(vh1, a1 + OVH);
            ldsm4t(vl0, a0 + OVL); ldsm4t(vl1, a1 + OVL);

            float* o0 = O[dp * 2];
            float* o1 = O[dp * 2 + 1];
            mma16816(o0, Ph[0], vh0);     mma16816(o1, Ph[0], vh0 + 2);
            mma16816(o0, Ph[1], vh1);     mma16816(o1, Ph[1], vh1 + 2);
            mma16816(o0, Ph[0], vl0);     mma16816(o1, Ph[0], vl0 + 2);
            mma16816(o0, Ph[1], vl1);     mma16816(o1, Ph[1], vl1 + 2);
            mma16816(o0, Pl[0], vh0);     mma16816(o1, Pl[0], vh0 + 2);
            mma16816(o0, Pl[1], vh1);     mma16816(o1, Pl[1], vh1 + 2);
        }
    }

    // ---- cross-kv-warp O reduction + normalize + store ----
    __syncthreads();
    if (kw == 1) {
        float* dst = sOred + qw * 16 * 128;
#pragma unroll
        for (int nt = 0; nt < 16; ++nt) {
            dst[g * 128 + nt * 8 + 2 * t]           = O[nt][0];
            dst[g * 128 + nt * 8 + 2 * t + 1]       = O[nt][1];
            dst[(g + 8) * 128 + nt * 8 + 2 * t]     = O[nt][2];
            dst[(g + 8) * 128 + nt * 8 + 2 * t + 1] = O[nt][3];
        }
    }
    __syncthreads();
    if (kw == 0) {
        const float* src = sOred + qw * 16 * 128;
        float inv0 = 1.f / l0, inv1 = 1.f / l1;
        float* out0 = g_xr + (qrow0 + qw * 16 + g) * 128;
        float* out1 = g_xr + (qrow0 + qw * 16 + g + 8) * 128;
#pragma unroll
        for (int nt = 0; nt < 16; ++nt) {
            int c0 = nt * 8 + 2 * t;
            float2 v0 = {(O[nt][0] + src[g * 128 + c0]) * inv0,
                         (O[nt][1] + src[g * 128 + c0 + 1]) * inv0};
            float2 v1 = {(O[nt][2] + src[(g + 8) * 128 + c0]) * inv1,
                         (O[nt][3] + src[(g + 8) * 128 + c0 + 1]) * inv1};
            *reinterpret_cast<float2*>(out0 + c0) = v0;
            *reinterpret_cast<float2*>(out1 + c0) = v1;
        }
    }
}

// ======================================================================
__global__ void k_stats()
{
    int f = threadIdx.x;
    float s = 0.f, q = 0.f;
    for (int b = 0; b < NQ / 64; ++b) {
        s += g_psum[b * 128 + f];
        q += g_psq [b * 128 + f];
    }
    float mean = s * (1.f / NQ);
    float var  = q * (1.f / NQ) - mean * mean;
    g_mean[f] = mean;
    g_rstd[f] = rsqrtf(var + BN_EPS);
}

__global__ void k_final(const float* __restrict__ gamma, const float* __restrict__ beta,
                        float* __restrict__ out)
{
    int idx = blockIdx.x * 256 + threadIdx.x;
    int f   = (idx & 31) * 4;
    float4 tv = *reinterpret_cast<const float4*>(g_t    + (size_t)idx * 4);
    float4 xd = *reinterpret_cast<const float4*>(g_xdec + (size_t)idx * 4);
    float4 r;
    r.x = xd.x + (tv.x - g_mean[f + 0]) * g_rstd[f + 0] * gamma[f + 0] + beta[f + 0];
    r.y = xd.y + (tv.y - g_mean[f + 1]) * g_rstd[f + 1] * gamma[f + 1] + beta[f + 1];
    r.z = xd.z + (tv.z - g_mean[f + 2]) * g_rstd[f + 2] * gamma[f + 2] + beta[f + 2];
    r.w = xd.w + (tv.w - g_mean[f + 3]) * g_rstd[f + 3] * gamma[f + 3] + beta[f + 3];
    *reinterpret_cast<float4*>(out + (size_t)idx * 4) = r;
}

// ======================================================================
extern "C" void kernel_launch(void* const* d_in, const int* in_sizes, int n_in,
                              void* d_out, int out_size)
{
    const float* xdec_f = (const float*)d_in[0];
    const float* xenc_f = (const float*)d_in[1];
    const int*   nbr    = (const int*)  d_in[2];
    const float* Wp1    = (const float*)d_in[3];
    const float* Wq     = (const float*)d_in[4];
    const float* Wk     = (const float*)d_in[5];
    const float* Wv     = (const float*)d_in[6];
    const float* Wt     = (const float*)d_in[7];
    const float* gamma  = (const float*)d_in[8];
    const float* beta   = (const float*)d_in[9];
    float* out = (float*)d_out;

    float *p_xdec, *p_xr, *p_t;
    __nv_bfloat16 *p_qh, *p_ql, *p_kh, *p_kl, *p_vh, *p_vl;
    cudaGetSymbolAddress((void**)&p_xdec, g_xdec);
    cudaGetSymbolAddress((void**)&p_xr,   g_xr);
    cudaGetSymbolAddress((void**)&p_t,    g_t);
    cudaGetSymbolAddress((void**)&p_qh,   g_qh);
    cudaGetSymbolAddress((void**)&p_ql,   g_ql);
    cudaGetSymbolAddress((void**)&p_kh,   g_kh);
    cudaGetSymbolAddress((void**)&p_kl,   g_kl);
    cudaGetSymbolAddress((void**)&p_vh,   g_vh);
    cudaGetSymbolAddress((void**)&p_vl,   g_vl);

    const int GSM = (64 * 68 + 64 * 128) * 4;
    cudaFuncSetAttribute(k_p1,               cudaFuncAttributeMaxDynamicSharedMemorySize, GSM);
    cudaFuncSetAttribute(k_gemm_split<64>,   cudaFuncAttributeMaxDynamicSharedMemorySize, GSM);
    cudaFuncSetAttribute(k_gemm_split<128>,  cudaFuncAttributeMaxDynamicSharedMemorySize, GSM);
    cudaFuncSetAttribute(k_gemm<128, true>,  cudaFuncAttributeMaxDynamicSharedMemorySize, GSM);
    cudaFuncSetAttribute(k_attn,             cudaFuncAttributeMaxDynamicSharedMemorySize, ASMSZ);

    k_p1<<<NQ / 64, 256, GSM>>>(xdec_f, nbr, Wp1);
    k_gemm_split<64><<<NKV / 64, 256, GSM>>>(xenc_f, Wk, p_kh, p_kl);
    k_gemm_split<64><<<NKV / 64, 256, GSM>>>(xenc_f, Wv, p_vh, p_vl);
    k_gemm_split<128><<<NQ / 64, 256, GSM>>>(p_xdec, Wq, p_qh, p_ql);
    k_attn<<<dim3(NQB / 64, NBATCH), 256, ASMSZ>>>();
    k_gemm<128, true><<<NQ / 64, 256, GSM>>>(p_xr, Wt, p_t);
    k_stats<<<1, 128>>>();
    k_final<<<(NQ * NF / 4) / 256, 256>>>(gamma, beta, out);
}

// round 4
// speedup vs baseline: 3.3110x; 1.4462x over previous
#include <cuda_runtime.h>
#include <cuda_bf16.h>
#include <cstdint>

#define NQ      16384
#define NKV     32768
#define DEC     64
#define NF      128
#define NBATCH  8
#define NQB     2048
#define NKB     4096
#define BN_EPS  1e-4f

// ---------------- scratch (alloc-free: device globals) ----------------
__device__ float g_xdec[NQ * NF];          // fp32 x_dec (residual)
__device__ float g_t   [NQ * NF];
__device__ float g_psum[(NQ / 64) * NF];
__device__ float g_psq [(NQ / 64) * NF];
__device__ float g_mean[NF];
__device__ float g_rstd[NF];
// split-bf16 operand pools
__device__ __nv_bfloat16 g_dfh[NQ * DEC],  g_dfl[NQ * DEC];    // x_decoder_feat
__device__ __nv_bfloat16 g_eh [NKV * DEC], g_el [NKV * DEC];   // x_encoder_feat
__device__ __nv_bfloat16 g_wp1h[27 * 64 * 128], g_wp1l[27 * 64 * 128];
__device__ __nv_bfloat16 g_wkh[64 * 128],  g_wkl[64 * 128];
__device__ __nv_bfloat16 g_wvh[64 * 128],  g_wvl[64 * 128];
__device__ __nv_bfloat16 g_wqh[128 * 128], g_wql[128 * 128];
__device__ __nv_bfloat16 g_wth[128 * 128], g_wtl[128 * 128];
__device__ __nv_bfloat16 g_xdh[NQ * NF],  g_xdl[NQ * NF];      // split x_dec
__device__ __nv_bfloat16 g_qh[NQ * NF],   g_ql[NQ * NF];
__device__ __nv_bfloat16 g_kh[NKV * NF],  g_kl[NKV * NF];
__device__ __nv_bfloat16 g_vh[NKV * NF],  g_vl[NKV * NF];
__device__ __nv_bfloat16 g_xrh[NQ * NF],  g_xrl[NQ * NF];      // split x_r

// ---------------- helpers ----------------
__device__ __forceinline__ uint32_t packb(__nv_bfloat16 x, __nv_bfloat16 y) {
    __nv_bfloat162 v(x, y);
    return *reinterpret_cast<uint32_t*>(&v);
}
__device__ __forceinline__ void split2(float a, float b, uint32_t& hi, uint32_t& lo) {
    __nv_bfloat16 ah = __float2bfloat16(a);
    __nv_bfloat16 bh = __float2bfloat16(b);
    float ar = a - __bfloat162float(ah);
    float br = b - __bfloat162float(bh);
    hi = packb(ah, bh);
    lo = packb(__float2bfloat16(ar), __float2bfloat16(br));
}
__device__ __forceinline__ void mma16816(float* d, const uint32_t* a, const uint32_t* b) {
    asm volatile("mma.sync.aligned.m16n8k16.row.col.f32.bf16.bf16.f32 "
                 "{%0,%1,%2,%3}, {%4,%5,%6,%7}, {%8,%9}, {%0,%1,%2,%3};"
                 : "+f"(d[0]), "+f"(d[1]), "+f"(d[2]), "+f"(d[3])
                 : "r"(a[0]), "r"(a[1]), "r"(a[2]), "r"(a[3]), "r"(b[0]), "r"(b[1]));
}
__device__ __forceinline__ void ldsm4(uint32_t* r, uint32_t addr) {
    asm volatile("ldmatrix.sync.aligned.m8n8.x4.shared.b16 {%0,%1,%2,%3}, [%4];"
                 : "=r"(r[0]), "=r"(r[1]), "=r"(r[2]), "=r"(r[3]) : "r"(addr));
}
__device__ __forceinline__ void ldsm4t(uint32_t* r, uint32_t addr) {
    asm volatile("ldmatrix.sync.aligned.m8n8.x4.trans.shared.b16 {%0,%1,%2,%3}, [%4];"
                 : "=r"(r[0]), "=r"(r[1]), "=r"(r[2]), "=r"(r[3]) : "r"(addr));
}

// ======================================================================
// Split-prep: all fp32 operands -> bf16 hi/lo
// ======================================================================
#define SB0 (NQ * DEC)                 // 1048576  xdec feat
#define SB1 (SB0 + NKV * DEC)          // 3145728  xenc feat
#define SB2 (SB1 + 27 * 64 * 128)      // 3366912  Wp1
#define SB3 (SB2 + 64 * 128)           // 3375104  Wk
#define SB4 (SB3 + 64 * 128)           // 3383296  Wv
#define SB5 (SB4 + 128 * 128)          // 3399680  Wq
#define SB6 (SB5 + 128 * 128)          // 3416064  Wt

__device__ __forceinline__ void split4(float4 v, uint2& h, uint2& l) {
    uint32_t h0, l0, h1, l1;
    split2(v.x, v.y, h0, l0);
    split2(v.z, v.w, h1, l1);
    h = {h0, h1};
    l = {l0, l1};
}

__global__ void k_split7(const float* __restrict__ xdf, const float* __restrict__ xef,
                         const float* __restrict__ Wp1, const float* __restrict__ Wk,
                         const float* __restrict__ Wv,  const float* __restrict__ Wq,
                         const float* __restrict__ Wt)
{
    int e = (blockIdx.x * 256 + threadIdx.x) * 4;
    const float* src; __nv_bfloat16 *dh, *dl; int off;
    if      (e < SB0) { src = xdf; dh = g_dfh;  dl = g_dfl;  off = e; }
    else if (e < SB1) { src = xef; dh = g_eh;   dl = g_el;   off = e - SB0; }
    else if (e < SB2) { src = Wp1; dh = g_wp1h; dl = g_wp1l; off = e - SB1; }
    else if (e < SB3) { src = Wk;  dh = g_wkh;  dl = g_wkl;  off = e - SB2; }
    else if (e < SB4) { src = Wv;  dh = g_wvh;  dl = g_wvl;  off = e - SB3; }
    else if (e < SB5) { src = Wq;  dh = g_wqh;  dl = g_wql;  off = e - SB4; }
    else              { src = Wt;  dh = g_wth;  dl = g_wtl;  off = e - SB5; }
    float4 v = *reinterpret_cast<const float4*>(src + off);
    uint2 h, l;
    split4(v, h, l);
    *reinterpret_cast<uint2*>(dh + off) = h;
    *reinterpret_cast<uint2*>(dl + off) = l;
}

// ======================================================================
// Shared MMA-tile machinery (64-row x 128-col block tile, 8 warps)
// smem: Ah[64][72] Al[64][72] Bh[64][136] Bl[64][136]  (bf16)
// ======================================================================
#define GOAH  0
#define GOAL  9216
#define GOBH  18432
#define GOBL  35840
#define GSMSZ 53248

__device__ __forceinline__ void mma_tile64(uint32_t sbase, int qw, int nw, int lane,
                                           float acc[8][4])
{
    const int rA = lane & 15, cA = (lane >> 4) * 8;
    const int rV = ((lane >> 3) & 1) * 8 + (lane & 7);
    const int cV = ((lane >> 3) & 2) * 4;
#pragma unroll
    for (int kc = 0; kc < 4; ++kc) {
        uint32_t Aaddr = sbase + (uint32_t)((qw * 16 + rA) * 72 + kc * 16 + cA) * 2;
        uint32_t Ah4[4], Al4[4];
        ldsm4(Ah4, Aaddr + GOAH);
        ldsm4(Al4, Aaddr + GOAL);
#pragma unroll
        for (int nt2 = 0; nt2 < 4; ++nt2) {
            uint32_t Baddr = sbase +
                (uint32_t)((kc * 16 + rV) * 136 + nw * 64 + nt2 * 16 + cV) * 2;
            uint32_t Bh4[4], Bl4[4];
            ldsm4t(Bh4, Baddr + GOBH);
            ldsm4t(Bl4, Baddr + GOBL);
            float* a0 = acc[nt2 * 2];
            float* a1 = acc[nt2 * 2 + 1];
            mma16816(a0, Ah4, Bh4);  mma16816(a1, Ah4, Bh4 + 2);
            mma16816(a0, Ah4, Bl4);  mma16816(a1, Ah4, Bl4 + 2);
            mma16816(a0, Al4, Bh4);  mma16816(a1, Al4, Bh4 + 2);
        }
    }
}

// ======================================================================
// p1 gather-conv via tensor cores: x_dec = sum_k gather(X,k) @ Wp1[k]
// Also emits split(x_dec) for the Q projection.
// ======================================================================
__global__ __launch_bounds__(256) void k_p1_mma(const int* __restrict__ nbr)
{
    extern __shared__ char smr[];
    const uint32_t sbase = (uint32_t)__cvta_generic_to_shared(smr);
    const int tid = threadIdx.x;
    const int wid = tid >> 5, lane = tid & 31;
    const int qw = wid >> 1, nw = wid & 1;
    const int m0 = blockIdx.x * 64;

    float acc[8][4];
#pragma unroll
    for (int i = 0; i < 8; ++i)
#pragma unroll
        for (int j = 0; j < 4; ++j) acc[i][j] = 0.f;

    for (int k = 0; k < 27; ++k) {
        __syncthreads();
        // gather A rows (hi/lo)
#pragma unroll
        for (int i = 0; i < 2; ++i) {
            int idx = tid + i * 256;          // 0..511
            int r = idx >> 3, c = idx & 7;
            int gi = nbr[(m0 + r) * 27 + k];
            *reinterpret_cast<uint4*>(smr + GOAH + (r * 72 + c * 8) * 2) =
                *reinterpret_cast<const uint4*>(g_dfh + (size_t)gi * DEC + c * 8);
            *reinterpret_cast<uint4*>(smr + GOAL + (r * 72 + c * 8) * 2) =
                *reinterpret_cast<const uint4*>(g_dfl + (size_t)gi * DEC + c * 8);
        }
        // W tap (hi/lo)
        const __nv_bfloat16* wh = g_wp1h + (size_t)k * 64 * 128;
        const __nv_bfloat16* wl = g_wp1l + (size_t)k * 64 * 128;
#pragma unroll
        for (int i = 0; i < 4; ++i) {
            int idx = tid + i * 256;          // 0..1023
            int r = idx >> 4, c = idx & 15;
            *reinterpret_cast<uint4*>(smr + GOBH + (r * 136 + c * 8) * 2) =
                *reinterpret_cast<const uint4*>(wh + r * 128 + c * 8);
            *reinterpret_cast<uint4*>(smr + GOBL + (r * 136 + c * 8) * 2) =
                *reinterpret_cast<const uint4*>(wl + r * 128 + c * 8);
        }
        __syncthreads();
        mma_tile64(sbase, qw, nw, lane, acc);
    }

    const int g = lane >> 2, t = lane & 3;
    const int r0 = m0 + qw * 16 + g, r1 = r0 + 8;
#pragma unroll
    for (int nt = 0; nt < 8; ++nt) {
        int col = nw * 64 + nt * 8 + 2 * t;
        float2 v0 = {acc[nt][0], acc[nt][1]};
        float2 v1 = {acc[nt][2], acc[nt][3]};
        *reinterpret_cast<float2*>(g_xdec + (size_t)r0 * 128 + col) = v0;
        *reinterpret_cast<float2*>(g_xdec + (size_t)r1 * 128 + col) = v1;
        uint32_t h, l;
        split2(v0.x, v0.y, h, l);
        *reinterpret_cast<uint32_t*>(g_xdh + (size_t)r0 * 128 + col) = h;
        *reinterpret_cast<uint32_t*>(g_xdl + (size_t)r0 * 128 + col) = l;
        split2(v1.x, v1.y, h, l);
        *reinterpret_cast<uint32_t*>(g_xdh + (size_t)r1 * 128 + col) = h;
        *reinterpret_cast<uint32_t*>(g_xdl + (size_t)r1 * 128 + col) = l;
    }
}

// ======================================================================
// Generic split-bf16 MMA GEMM: C[M,128] = (Ah+Al)[M,KA] @ (Bh+Bl)[KA,128]
// SPLIT=true  -> write bf16 hi/lo outputs
// SPLIT=false -> write fp32 output
// ======================================================================
template <int KA, bool SPLIT>
__global__ __launch_bounds__(256) void k_proj(const __nv_bfloat16* __restrict__ Ahg,
                                              const __nv_bfloat16* __restrict__ Alg,
                                              const __nv_bfloat16* __restrict__ Bhg,
                                              const __nv_bfloat16* __restrict__ Blg,
                                              __nv_bfloat16* __restrict__ Ch,
                                              __nv_bfloat16* __restrict__ Cl,
                                              float* __restrict__ Cf)
{
    extern __shared__ char smr[];
    const uint32_t sbase = (uint32_t)__cvta_generic_to_shared(smr);
    const int tid = threadIdx.x;
    const int wid = tid >> 5, lane = tid & 31;
    const int qw = wid >> 1, nw = wid & 1;
    const int m0 = blockIdx.x * 64;

    float acc[8][4];
#pragma unroll
    for (int i = 0; i < 8; ++i)
#pragma unroll
        for (int j = 0; j < 4; ++j) acc[i][j] = 0.f;

#pragma unroll
    for (int kb = 0; kb < KA / 64; ++kb) {
        __syncthreads();
#pragma unroll
        for (int i = 0; i < 2; ++i) {
            int idx = tid + i * 256;
            int r = idx >> 3, c = idx & 7;
            size_t go = (size_t)(m0 + r) * KA + kb * 64 + c * 8;
            *reinterpret_cast<uint4*>(smr + GOAH + (r * 72 + c * 8) * 2) =
                *reinterpret_cast<const uint4*>(Ahg + go);
            *reinterpret_cast<uint4*>(smr + GOAL + (r * 72 + c * 8) * 2) =
                *reinterpret_cast<const uint4*>(Alg + go);
        }
#pragma unroll
        for (int i = 0; i < 4; ++i) {
            int idx = tid + i * 256;
            int r = idx >> 4, c = idx & 15;
            size_t go = (size_t)(kb * 64 + r) * 128 + c * 8;
            *reinterpret_cast<uint4*>(smr + GOBH + (r * 136 + c * 8) * 2) =
                *reinterpret_cast<const uint4*>(Bhg + go);
            *reinterpret_cast<uint4*>(smr + GOBL + (r * 136 + c * 8) * 2) =
                *reinterpret_cast<const uint4*>(Blg + go);
        }
        __syncthreads();
        mma_tile64(sbase, qw, nw, lane, acc);
    }

    const int g = lane >> 2, t = lane & 3;
    const int r0 = m0 + qw * 16 + g, r1 = r0 + 8;
#pragma unroll
    for (int nt = 0; nt < 8; ++nt) {
        int col = nw * 64 + nt * 8 + 2 * t;
        if (SPLIT) {
            uint32_t h, l;
            split2(acc[nt][0], acc[nt][1], h, l);
            *reinterpret_cast<uint32_t*>(Ch + (size_t)r0 * 128 + col) = h;
            *reinterpret_cast<uint32_t*>(Cl + (size_t)r0 * 128 + col) = l;
            split2(acc[nt][2], acc[nt][3], h, l);
            *reinterpret_cast<uint32_t*>(Ch + (size_t)r1 * 128 + col) = h;
            *reinterpret_cast<uint32_t*>(Cl + (size_t)r1 * 128 + col) = l;
        } else {
            float2 v0 = {acc[nt][0], acc[nt][1]};
            float2 v1 = {acc[nt][2], acc[nt][3]};
            *reinterpret_cast<float2*>(Cf + (size_t)r0 * 128 + col) = v0;
            *reinterpret_cast<float2*>(Cf + (size_t)r1 * 128 + col) = v1;
        }
    }
}

// ======================================================================
// Flash attention with bf16-split tensor-core MMA (as round 3),
// epilogue writes split bf16 x_r.
// ======================================================================
#define TB    (64 * 136 * 2)
#define OKH   0
#define OKL   (TB)
#define OVH   (2 * TB)
#define OVL   (3 * TB)
#define OQH   (4 * TB)
#define OQL   (5 * TB)
#define OSTAT (6 * TB)
#define ASMSZ (OSTAT + 256 * 4)

__global__ __launch_bounds__(256) void k_attn()
{
    extern __shared__ char smr[];
    const uint32_t sbase = (uint32_t)__cvta_generic_to_shared(smr);
    float* sMax = reinterpret_cast<float*>(smr + OSTAT);
    float* sSum = reinterpret_cast<float*>(smr + OSTAT + 512);
    float* sOred = reinterpret_cast<float*>(smr);

    const int tid  = threadIdx.x;
    const int wid  = tid >> 5, lane = tid & 31;
    const int qw   = wid >> 1, kw = wid & 1;
    const int g    = lane >> 2, t = lane & 3;
    const int b    = blockIdx.y;
    const size_t qrow0 = (size_t)b * NQB + blockIdx.x * 64;

    const int rA = lane & 15;
    const int cA = (lane >> 4) * 8;
    const int rB = ((lane >> 3) & 2) * 4 + (lane & 7);
    const int cB = ((lane >> 3) & 1) * 8;
    const int rV = ((lane >> 3) & 1) * 8 + (lane & 7);
    const int cV = ((lane >> 3) & 2) * 4;

    {
        const __nv_bfloat16* qh = g_qh + qrow0 * 128;
        const __nv_bfloat16* ql = g_ql + qrow0 * 128;
        __nv_bfloat16* sqh = reinterpret_cast<__nv_bfloat16*>(smr + OQH);
        __nv_bfloat16* sql = reinterpret_cast<__nv_bfloat16*>(smr + OQL);
#pragma unroll
        for (int i = 0; i < 4; ++i) {
            int idx = tid + i * 256;
            int r = idx >> 4, c = idx & 15;
            *reinterpret_cast<uint4*>(sqh + r * 136 + c * 8) =
                *reinterpret_cast<const uint4*>(qh + (size_t)r * 128 + c * 8);
            *reinterpret_cast<uint4*>(sql + r * 136 + c * 8) =
                *reinterpret_cast<const uint4*>(ql + (size_t)r * 128 + c * 8);
        }
    }

    float O[16][4];
#pragma unroll
    for (int i = 0; i < 16; ++i)
#pragma unroll
        for (int j = 0; j < 4; ++j) O[i][j] = 0.f;
    float m0r = -1e30f, m1r = -1e30f, l0 = 0.f, l1 = 0.f;

    for (int jt = 0; jt < NKB / 64; ++jt) {
        __syncthreads();
        {
            size_t base = ((size_t)b * NKB + jt * 64) * 128;
            __nv_bfloat16* skh = reinterpret_cast<__nv_bfloat16*>(smr + OKH);
            __nv_bfloat16* skl = reinterpret_cast<__nv_bfloat16*>(smr + OKL);
            __nv_bfloat16* svh = reinterpret_cast<__nv_bfloat16*>(smr + OVH);
            __nv_bfloat16* svl = reinterpret_cast<__nv_bfloat16*>(smr + OVL);
#pragma unroll
            for (int i = 0; i < 4; ++i) {
                int idx = tid + i * 256;
                int r = idx >> 4, c = idx & 15;
                size_t go = base + (size_t)r * 128 + c * 8;
                int so = r * 136 + c * 8;
                *reinterpret_cast<uint4*>(skh + so) = *reinterpret_cast<const uint4*>(g_kh + go);
                *reinterpret_cast<uint4*>(skl + so) = *reinterpret_cast<const uint4*>(g_kl + go);
                *reinterpret_cast<uint4*>(svh + so) = *reinterpret_cast<const uint4*>(g_vh + go);
                *reinterpret_cast<uint4*>(svl + so) = *reinterpret_cast<const uint4*>(g_vl + go);
            }
        }
        __syncthreads();

        float sA[4][4];
#pragma unroll
        for (int i = 0; i < 4; ++i)
#pragma unroll
            for (int j = 0; j < 4; ++j) sA[i][j] = 0.f;

#pragma unroll
        for (int ch = 0; ch < 8; ++ch) {
            uint32_t Aaddr = sbase + (uint32_t)((qw * 16 + rA) * 136 + ch * 16 + cA) * 2;
            uint32_t Ah[4], Al[4];
            ldsm4(Ah, Aaddr + OQH);
            ldsm4(Al, Aaddr + OQL);

            uint32_t col = (uint32_t)(ch * 16 + cB) * 2;
            uint32_t a0 = sbase + (uint32_t)((kw * 32 + rB) * 136) * 2 + col;
            uint32_t a1 = sbase + (uint32_t)((kw * 32 + 16 + rB) * 136) * 2 + col;
            uint32_t bh0[4], bh1[4], bl0[4], bl1[4];
            ldsm4(bh0, a0 + OKH); ldsm4(bh1, a1 + OKH);
            ldsm4(bl0, a0 + OKL); ldsm4(bl1, a1 + OKL);

            mma16816(sA[0], Ah, bh0);     mma16816(sA[1], Ah, bh0 + 2);
            mma16816(sA[2], Ah, bh1);     mma16816(sA[3], Ah, bh1 + 2);
            mma16816(sA[0], Ah, bl0);     mma16816(sA[1], Ah, bl0 + 2);
            mma16816(sA[2], Ah, bl1);     mma16816(sA[3], Ah, bl1 + 2);
            mma16816(sA[0], Al, bh0);     mma16816(sA[1], Al, bh0 + 2);
            mma16816(sA[2], Al, bh1);     mma16816(sA[3], Al, bh1 + 2);
        }

        float rm0 = sA[0][0], rm1 = sA[0][2];
#pragma unroll
        for (int nt = 0; nt < 4; ++nt) {
            rm0 = fmaxf(rm0, fmaxf(sA[nt][0], sA[nt][1]));
            rm1 = fmaxf(rm1, fmaxf(sA[nt][2], sA[nt][3]));
        }
        rm0 = fmaxf(rm0, __shfl_xor_sync(0xffffffffu, rm0, 1));
        rm0 = fmaxf(rm0, __shfl_xor_sync(0xffffffffu, rm0, 2));
        rm1 = fmaxf(rm1, __shfl_xor_sync(0xffffffffu, rm1, 1));
        rm1 = fmaxf(rm1, __shfl_xor_sync(0xffffffffu, rm1, 2));
        if (t == 0) {
            sMax[(qw * 2 + kw) * 16 + g]     = rm0;
            sMax[(qw * 2 + kw) * 16 + g + 8] = rm1;
        }
        asm volatile("bar.sync %0, %1;" :: "r"(qw + 1), "r"(64) : "memory");
        float om0 = sMax[(qw * 2 + (kw ^ 1)) * 16 + g];
        float om1 = sMax[(qw * 2 + (kw ^ 1)) * 16 + g + 8];
        float mn0 = fmaxf(m0r, fmaxf(rm0, om0));
        float mn1 = fmaxf(m1r, fmaxf(rm1, om1));
        float sc0 = __expf(m0r - mn0);
        float sc1 = __expf(m1r - mn1);

        float p[4][4];
        float ls0 = 0.f, ls1 = 0.f;
#pragma unroll
        for (int nt = 0; nt < 4; ++nt) {
            p[nt][0] = __expf(sA[nt][0] - mn0);
            p[nt][1] = __expf(sA[nt][1] - mn0);
            p[nt][2] = __expf(sA[nt][2] - mn1);
            p[nt][3] = __expf(sA[nt][3] - mn1);
            ls0 += p[nt][0] + p[nt][1];
            ls1 += p[nt][2] + p[nt][3];
        }
        ls0 += __shfl_xor_sync(0xffffffffu, ls0, 1);
        ls0 += __shfl_xor_sync(0xffffffffu, ls0, 2);
        ls1 += __shfl_xor_sync(0xffffffffu, ls1, 1);
        ls1 += __shfl_xor_sync(0xffffffffu, ls1, 2);
        if (t == 0) {
            sSum[(qw * 2 + kw) * 16 + g]     = ls0;
            sSum[(qw * 2 + kw) * 16 + g + 8] = ls1;
        }
        asm volatile("bar.sync %0, %1;" :: "r"(qw + 1), "r"(64) : "memory");
        float os0 = sSum[(qw * 2 + (kw ^ 1)) * 16 + g];
        float os1 = sSum[(qw * 2 + (kw ^ 1)) * 16 + g + 8];
        l0 = l0 * sc0 + ls0 + os0;
        l1 = l1 * sc1 + ls1 + os1;
        m0r = mn0; m1r = mn1;

#pragma unroll
        for (int nt = 0; nt < 16; ++nt) {
            O[nt][0] *= sc0; O[nt][1] *= sc0;
            O[nt][2] *= sc1; O[nt][3] *= sc1;
        }

        uint32_t Ph[2][4], Pl[2][4];
#pragma unroll
        for (int c = 0; c < 2; ++c) {
            split2(p[2 * c][0],     p[2 * c][1],     Ph[c][0], Pl[c][0]);
            split2(p[2 * c][2],     p[2 * c][3],     Ph[c][1], Pl[c][1]);
            split2(p[2 * c + 1][0], p[2 * c + 1][1], Ph[c][2], Pl[c][2]);
            split2(p[2 * c + 1][2], p[2 * c + 1][3], Ph[c][3], Pl[c][3]);
        }

#pragma unroll
        for (int dp = 0; dp < 8; ++dp) {
            uint32_t col = (uint32_t)(dp * 16 + cV) * 2;
            uint32_t a0 = sbase + (uint32_t)((kw * 32 + rV) * 136) * 2 + col;
            uint32_t a1 = sbase + (uint32_t)((kw * 32 + 16 + rV) * 136) * 2 + col;
            uint32_t vh0[4], vh1[4], vl0[4], vl1[4];
            ldsm4t(vh0, a0 + OVH); ldsm4t(vh1, a1 + OVH);
            ldsm4t(vl0, a0 + OVL); ldsm4t(vl1, a1 + OVL);

            float* o0 = O[dp * 2];
            float* o1 = O[dp * 2 + 1];
            mma16816(o0, Ph[0], vh0);     mma16816(o1, Ph[0], vh0 + 2);
            mma16816(o0, Ph[1], vh1);     mma16816(o1, Ph[1], vh1 + 2);
            mma16816(o0, Ph[0], vl0);     mma16816(o1, Ph[0], vl0 + 2);
            mma16816(o0, Ph[1], vl1);     mma16816(o1, Ph[1], vl1 + 2);
            mma16816(o0, Pl[0], vh0);     mma16816(o1, Pl[0], vh0 + 2);
            mma16816(o0, Pl[1], vh1);     mma16816(o1, Pl[1], vh1 + 2);
        }
    }

    __syncthreads();
    if (kw == 1) {
        float* dst = sOred + qw * 16 * 128;
#pragma unroll
        for (int nt = 0; nt < 16; ++nt) {
            dst[g * 128 + nt * 8 + 2 * t]           = O[nt][0];
            dst[g * 128 + nt * 8 + 2 * t + 1]       = O[nt][1];
            dst[(g + 8) * 128 + nt * 8 + 2 * t]     = O[nt][2];
            dst[(g + 8) * 128 + nt * 8 + 2 * t + 1] = O[nt][3];
        }
    }
    __syncthreads();
    if (kw == 0) {
        const float* src = sOred + qw * 16 * 128;
        float inv0 = 1.f / l0, inv1 = 1.f / l1;
        size_t out0 = (qrow0 + qw * 16 + g) * 128;
        size_t out1 = (qrow0 + qw * 16 + g + 8) * 128;
#pragma unroll
        for (int nt = 0; nt < 16; ++nt) {
            int c0 = nt * 8 + 2 * t;
            float a0 = (O[nt][0] + src[g * 128 + c0]) * inv0;
            float a1 = (O[nt][1] + src[g * 128 + c0 + 1]) * inv0;
            float b0v = (O[nt][2] + src[(g + 8) * 128 + c0]) * inv1;
            float b1v = (O[nt][3] + src[(g + 8) * 128 + c0 + 1]) * inv1;
            uint32_t h, l;
            split2(a0, a1, h, l);
            *reinterpret_cast<uint32_t*>(g_xrh + out0 + c0) = h;
            *reinterpret_cast<uint32_t*>(g_xrl + out0 + c0) = l;
            split2(b0v, b1v, h, l);
            *reinterpret_cast<uint32_t*>(g_xrh + out1 + c0) = h;
            *reinterpret_cast<uint32_t*>(g_xrl + out1 + c0) = l;
        }
    }
}

// ======================================================================
// BN: per-block column stats over g_t, then finalize, then epilogue
// ======================================================================
__global__ void k_colstats()
{
    int f = threadIdx.x;                      // 0..127
    const float* base = g_t + (size_t)blockIdx.x * 64 * 128;
    float s = 0.f, q = 0.f;
#pragma unroll 8
    for (int r = 0; r < 64; ++r) {
        float v = base[r * 128 + f];
        s += v; q += v * v;
    }
    g_psum[blockIdx.x * 128 + f] = s;
    g_psq [blockIdx.x * 128 + f] = q;
}

__global__ void k_stats()
{
    int f = threadIdx.x;
    float s = 0.f, q = 0.f;
    for (int b = 0; b < NQ / 64; ++b) {
        s += g_psum[b * 128 + f];
        q += g_psq [b * 128 + f];
    }
    float mean = s * (1.f / NQ);
    float var  = q * (1.f / NQ) - mean * mean;
    g_mean[f] = mean;
    g_rstd[f] = rsqrtf(var + BN_EPS);
}

__global__ void k_final(const float* __restrict__ gamma, const float* __restrict__ beta,
                        float* __restrict__ out)
{
    int idx = blockIdx.x * 256 + threadIdx.x;
    int f   = (idx & 31) * 4;
    float4 tv = *reinterpret_cast<const float4*>(g_t    + (size_t)idx * 4);
    float4 xd = *reinterpret_cast<const float4*>(g_xdec + (size_t)idx * 4);
    float4 r;
    r.x = xd.x + (tv.x - g_mean[f + 0]) * g_rstd[f + 0] * gamma[f + 0] + beta[f + 0];
    r.y = xd.y + (tv.y - g_mean[f + 1]) * g_rstd[f + 1] * gamma[f + 1] + beta[f + 1];
    r.z = xd.z + (tv.z - g_mean[f + 2]) * g_rstd[f + 2] * gamma[f + 2] + beta[f + 2];
    r.w = xd.w + (tv.w - g_mean[f + 3]) * g_rstd[f + 3] * gamma[f + 3] + beta[f + 3];
    *reinterpret_cast<float4*>(out + (size_t)idx * 4) = r;
}

// ======================================================================
extern "C" void kernel_launch(void* const* d_in, const int* in_sizes, int n_in,
                              void* d_out, int out_size)
{
    const float* xdec_f = (const float*)d_in[0];
    const float* xenc_f = (const float*)d_in[1];
    const int*   nbr    = (const int*)  d_in[2];
    const float* Wp1    = (const float*)d_in[3];
    const float* Wq     = (const float*)d_in[4];
    const float* Wk     = (const float*)d_in[5];
    const float* Wv     = (const float*)d_in[6];
    const float* Wt     = (const float*)d_in[7];
    const float* gamma  = (const float*)d_in[8];
    const float* beta   = (const float*)d_in[9];
    float* out = (float*)d_out;

    __nv_bfloat16 *p_eh, *p_el, *p_xdh, *p_xdl, *p_xrh, *p_xrl;
    __nv_bfloat16 *p_wkh, *p_wkl, *p_wvh, *p_wvl, *p_wqh, *p_wql, *p_wth, *p_wtl;
    __nv_bfloat16 *p_qh, *p_ql, *p_kh, *p_kl, *p_vh, *p_vl;
    float *p_t;
    cudaGetSymbolAddress((void**)&p_eh,  g_eh);   cudaGetSymbolAddress((void**)&p_el,  g_el);
    cudaGetSymbolAddress((void**)&p_xdh, g_xdh);  cudaGetSymbolAddress((void**)&p_xdl, g_xdl);
    cudaGetSymbolAddress((void**)&p_xrh, g_xrh);  cudaGetSymbolAddress((void**)&p_xrl, g_xrl);
    cudaGetSymbolAddress((void**)&p_wkh, g_wkh);  cudaGetSymbolAddress((void**)&p_wkl, g_wkl);
    cudaGetSymbolAddress((void**)&p_wvh, g_wvh);  cudaGetSymbolAddress((void**)&p_wvl, g_wvl);
    cudaGetSymbolAddress((void**)&p_wqh, g_wqh);  cudaGetSymbolAddress((void**)&p_wql, g_wql);
    cudaGetSymbolAddress((void**)&p_wth, g_wth);  cudaGetSymbolAddress((void**)&p_wtl, g_wtl);
    cudaGetSymbolAddress((void**)&p_qh,  g_qh);   cudaGetSymbolAddress((void**)&p_ql,  g_ql);
    cudaGetSymbolAddress((void**)&p_kh,  g_kh);   cudaGetSymbolAddress((void**)&p_kl,  g_kl);
    cudaGetSymbolAddress((void**)&p_vh,  g_vh);   cudaGetSymbolAddress((void**)&p_vl,  g_vl);
    cudaGetSymbolAddress((void**)&p_t,   g_t);

    cudaFuncSetAttribute(k_p1_mma,          cudaFuncAttributeMaxDynamicSharedMemorySize, GSMSZ);
    cudaFuncSetAttribute(k_proj<64,  true>, cudaFuncAttributeMaxDynamicSharedMemorySize, GSMSZ);
    cudaFuncSetAttribute(k_proj<128, true>, cudaFuncAttributeMaxDynamicSharedMemorySize, GSMSZ);
    cudaFuncSetAttribute(k_proj<128, false>,cudaFuncAttributeMaxDynamicSharedMemorySize, GSMSZ);
    cudaFuncSetAttribute(k_attn,            cudaFuncAttributeMaxDynamicSharedMemorySize, ASMSZ);

    k_split7<<<SB6 / 1024, 256>>>(xdec_f, xenc_f, Wp1, Wk, Wv, Wq, Wt);
    k_p1_mma<<<NQ / 64, 256, GSMSZ>>>(nbr);
    k_proj<64,  true><<<NKV / 64, 256, GSMSZ>>>(p_eh, p_el, p_wkh, p_wkl, p_kh, p_kl, nullptr);
    k_proj<64,  true><<<NKV / 64, 256, GSMSZ>>>(p_eh, p_el, p_wvh, p_wvl, p_vh, p_vl, nullptr);
    k_proj<128, true><<<NQ / 64, 256, GSMSZ>>>(p_xdh, p_xdl, p_wqh, p_wql, p_qh, p_ql, nullptr);
    k_attn<<<dim3(NQB / 64, NBATCH), 256, ASMSZ>>>();
    k_proj<128, false><<<NQ / 64, 256, GSMSZ>>>(p_xrh, p_xrl, p_wth, p_wtl, nullptr, nullptr, p_t);
    k_colstats<<<NQ / 64, 128>>>();
    k_stats<<<1, 128>>>();
    k_final<<<(NQ * NF / 4) / 256, 256>>>(gamma, beta, out);
}

// round 6
// speedup vs baseline: 4.2255x; 1.2762x over previous
#include <cuda_runtime.h>
#include <cuda_bf16.h>
#include <cstdint>

#define NQ      16384
#define NKV     32768
#define DEC     64
#define NF      128
#define NBATCH  8
#define NQB     2048
#define NKB     4096
#define BN_EPS  1e-4f

// ---------------- scratch (alloc-free: device globals) ----------------
__device__ float g_xdec[NQ * NF];
__device__ float g_t   [NQ * NF];
__device__ float g_psum[(NQ / 64) * NF];
__device__ float g_psq [(NQ / 64) * NF];
__device__ float g_mean[NF];
__device__ float g_rstd[NF];
__device__ __nv_bfloat16 g_dfh[NQ * DEC],  g_dfl[NQ * DEC];
__device__ __nv_bfloat16 g_eh [NKV * DEC], g_el [NKV * DEC];
__device__ __nv_bfloat16 g_wp1h[27 * 64 * 128], g_wp1l[27 * 64 * 128];
__device__ __nv_bfloat16 g_wkh[64 * 128],  g_wkl[64 * 128];
__device__ __nv_bfloat16 g_wvh[64 * 128],  g_wvl[64 * 128];
__device__ __nv_bfloat16 g_wqh[128 * 128], g_wql[128 * 128];
__device__ __nv_bfloat16 g_wth[128 * 128], g_wtl[128 * 128];
__device__ __nv_bfloat16 g_xdh[NQ * NF],  g_xdl[NQ * NF];
__device__ __nv_bfloat16 g_qh[NQ * NF],   g_ql[NQ * NF];
__device__ __nv_bfloat16 g_kh[NKV * NF],  g_kl[NKV * NF];
__device__ __nv_bfloat16 g_vh[NKV * NF],  g_vl[NKV * NF];
__device__ __nv_bfloat16 g_xrh[NQ * NF],  g_xrl[NQ * NF];

// ---------------- helpers ----------------
__device__ __forceinline__ uint32_t packb(__nv_bfloat16 x, __nv_bfloat16 y) {
    __nv_bfloat162 v(x, y);
    return *reinterpret_cast<uint32_t*>(&v);
}
__device__ __forceinline__ void split2(float a, float b, uint32_t& hi, uint32_t& lo) {
    __nv_bfloat16 ah = __float2bfloat16(a);
    __nv_bfloat16 bh = __float2bfloat16(b);
    float ar = a - __bfloat162float(ah);
    float br = b - __bfloat162float(bh);
    hi = packb(ah, bh);
    lo = packb(__float2bfloat16(ar), __float2bfloat16(br));
}
__device__ __forceinline__ void mma16816(float* d, const uint32_t* a, const uint32_t* b) {
    asm volatile("mma.sync.aligned.m16n8k16.row.col.f32.bf16.bf16.f32 "
                 "{%0,%1,%2,%3}, {%4,%5,%6,%7}, {%8,%9}, {%0,%1,%2,%3};"
                 : "+f"(d[0]), "+f"(d[1]), "+f"(d[2]), "+f"(d[3])
                 : "r"(a[0]), "r"(a[1]), "r"(a[2]), "r"(a[3]), "r"(b[0]), "r"(b[1]));
}
__device__ __forceinline__ void ldsm4(uint32_t* r, uint32_t addr) {
    asm volatile("ldmatrix.sync.aligned.m8n8.x4.shared.b16 {%0,%1,%2,%3}, [%4];"
                 : "=r"(r[0]), "=r"(r[1]), "=r"(r[2]), "=r"(r[3]) : "r"(addr));
}
__device__ __forceinline__ void ldsm4t(uint32_t* r, uint32_t addr) {
    asm volatile("ldmatrix.sync.aligned.m8n8.x4.trans.shared.b16 {%0,%1,%2,%3}, [%4];"
                 : "=r"(r[0]), "=r"(r[1]), "=r"(r[2]), "=r"(r[3]) : "r"(addr));
}
__device__ __forceinline__ void cpa16(uint32_t dst, const void* src) {
    asm volatile("cp.async.cg.shared.global [%0], [%1], 16;" :: "r"(dst), "l"(src));
}
__device__ __forceinline__ void cpa_commit() {
    asm volatile("cp.async.commit_group;");
}

// ======================================================================
// Split-prep
// ======================================================================
#define SB0 (NQ * DEC)
#define SB1 (SB0 + NKV * DEC)
#define SB2 (SB1 + 27 * 64 * 128)
#define SB3 (SB2 + 64 * 128)
#define SB4 (SB3 + 64 * 128)
#define SB5 (SB4 + 128 * 128)
#define SB6 (SB5 + 128 * 128)

__device__ __forceinline__ void split4(float4 v, uint2& h, uint2& l) {
    uint32_t h0, l0, h1, l1;
    split2(v.x, v.y, h0, l0);
    split2(v.z, v.w, h1, l1);
    h = {h0, h1};
    l = {l0, l1};
}

__global__ void k_split7(const float* __restrict__ xdf, const float* __restrict__ xef,
                         const float* __restrict__ Wp1, const float* __restrict__ Wk,
                         const float* __restrict__ Wv,  const float* __restrict__ Wq,
                         const float* __restrict__ Wt)
{
    int e = (blockIdx.x * 256 + threadIdx.x) * 4;
    const float* src; __nv_bfloat16 *dh, *dl; int off;
    if      (e < SB0) { src = xdf; dh = g_dfh;  dl = g_dfl;  off = e; }
    else if (e < SB1) { src = xef; dh = g_eh;   dl = g_el;   off = e - SB0; }
    else if (e < SB2) { src = Wp1; dh = g_wp1h; dl = g_wp1l; off = e - SB1; }
    else if (e < SB3) { src = Wk;  dh = g_wkh;  dl = g_wkl;  off = e - SB2; }
    else if (e < SB4) { src = Wv;  dh = g_wvh;  dl = g_wvl;  off = e - SB3; }
    else if (e < SB5) { src = Wq;  dh = g_wqh;  dl = g_wql;  off = e - SB4; }
    else              { src = Wt;  dh = g_wth;  dl = g_wtl;  off = e - SB5; }
    float4 v = *reinterpret_cast<const float4*>(src + off);
    uint2 h, l;
    split4(v, h, l);
    *reinterpret_cast<uint2*>(dh + off) = h;
    *reinterpret_cast<uint2*>(dl + off) = l;
}

// ======================================================================
// Shared MMA-tile machinery for GEMMs (64x128 tile, 8 warps)
// ======================================================================
#define GOAH  0
#define GOAL  9216
#define GOBH  18432
#define GOBL  35840
#define GSMSZ 53248

__device__ __forceinline__ void mma_tile64(uint32_t sbase, int qw, int nw, int lane,
                                           float acc[8][4])
{
    const int rA = lane & 15, cA = (lane >> 4) * 8;
    const int rV = ((lane >> 3) & 1) * 8 + (lane & 7);
    const int cV = ((lane >> 3) & 2) * 4;
#pragma unroll
    for (int kc = 0; kc < 4; ++kc) {
        uint32_t Aaddr = sbase + (uint32_t)((qw * 16 + rA) * 72 + kc * 16 + cA) * 2;
        uint32_t Ah4[4], Al4[4];
        ldsm4(Ah4, Aaddr + GOAH);
        ldsm4(Al4, Aaddr + GOAL);
#pragma unroll
        for (int nt2 = 0; nt2 < 4; ++nt2) {
            uint32_t Baddr = sbase +
                (uint32_t)((kc * 16 + rV) * 136 + nw * 64 + nt2 * 16 + cV) * 2;
            uint32_t Bh4[4], Bl4[4];
            ldsm4t(Bh4, Baddr + GOBH);
            ldsm4t(Bl4, Baddr + GOBL);
            float* a0 = acc[nt2 * 2];
            float* a1 = acc[nt2 * 2 + 1];
            mma16816(a0, Ah4, Bh4);  mma16816(a1, Ah4, Bh4 + 2);
            mma16816(a0, Ah4, Bl4);  mma16816(a1, Ah4, Bl4 + 2);
            mma16816(a0, Al4, Bh4);  mma16816(a1, Al4, Bh4 + 2);
        }
    }
}

// ======================================================================
// p1 gather-conv via tensor cores
// ======================================================================
__global__ __launch_bounds__(256) void k_p1_mma(const int* __restrict__ nbr)
{
    extern __shared__ char smr[];
    const uint32_t sbase = (uint32_t)__cvta_generic_to_shared(smr);
    const int tid = threadIdx.x;
    const int wid = tid >> 5, lane = tid & 31;
    const int qw = wid >> 1, nw = wid & 1;
    const int m0 = blockIdx.x * 64;

    float acc[8][4];
#pragma unroll
    for (int i = 0; i < 8; ++i)
#pragma unroll
        for (int j = 0; j < 4; ++j) acc[i][j] = 0.f;

    for (int k = 0; k < 27; ++k) {
        __syncthreads();
#pragma unroll
        for (int i = 0; i < 2; ++i) {
            int idx = tid + i * 256;
            int r = idx >> 3, c = idx & 7;
            int gi = nbr[(m0 + r) * 27 + k];
            *reinterpret_cast<uint4*>(smr + GOAH + (r * 72 + c * 8) * 2) =
                *reinterpret_cast<const uint4*>(g_dfh + (size_t)gi * DEC + c * 8);
            *reinterpret_cast<uint4*>(smr + GOAL + (r * 72 + c * 8) * 2) =
                *reinterpret_cast<const uint4*>(g_dfl + (size_t)gi * DEC + c * 8);
        }
        const __nv_bfloat16* wh = g_wp1h + (size_t)k * 64 * 128;
        const __nv_bfloat16* wl = g_wp1l + (size_t)k * 64 * 128;
#pragma unroll
        for (int i = 0; i < 4; ++i) {
            int idx = tid + i * 256;
            int r = idx >> 4, c = idx & 15;
            *reinterpret_cast<uint4*>(smr + GOBH + (r * 136 + c * 8) * 2) =
                *reinterpret_cast<const uint4*>(wh + r * 128 + c * 8);
            *reinterpret_cast<uint4*>(smr + GOBL + (r * 136 + c * 8) * 2) =
                *reinterpret_cast<const uint4*>(wl + r * 128 + c * 8);
        }
        __syncthreads();
        mma_tile64(sbase, qw, nw, lane, acc);
    }

    const int g = lane >> 2, t = lane & 3;
    const int r0 = m0 + qw * 16 + g, r1 = r0 + 8;
#pragma unroll
    for (int nt = 0; nt < 8; ++nt) {
        int col = nw * 64 + nt * 8 + 2 * t;
        float2 v0 = {acc[nt][0], acc[nt][1]};
        float2 v1 = {acc[nt][2], acc[nt][3]};
        *reinterpret_cast<float2*>(g_xdec + (size_t)r0 * 128 + col) = v0;
        *reinterpret_cast<float2*>(g_xdec + (size_t)r1 * 128 + col) = v1;
        uint32_t h, l;
        split2(v0.x, v0.y, h, l);
        *reinterpret_cast<uint32_t*>(g_xdh + (size_t)r0 * 128 + col) = h;
        *reinterpret_cast<uint32_t*>(g_xdl + (size_t)r0 * 128 + col) = l;
        split2(v1.x, v1.y, h, l);
        *reinterpret_cast<uint32_t*>(g_xdh + (size_t)r1 * 128 + col) = h;
        *reinterpret_cast<uint32_t*>(g_xdl + (size_t)r1 * 128 + col) = l;
    }
}

// ======================================================================
// Generic split-bf16 MMA GEMM
// ======================================================================
template <int KA, bool SPLIT>
__global__ __launch_bounds__(256) void k_proj(const __nv_bfloat16* __restrict__ Ahg,
                                              const __nv_bfloat16* __restrict__ Alg,
                                              const __nv_bfloat16* __restrict__ Bhg,
                                              const __nv_bfloat16* __restrict__ Blg,
                                              __nv_bfloat16* __restrict__ Ch,
                                              __nv_bfloat16* __restrict__ Cl,
                                              float* __restrict__ Cf)
{
    extern __shared__ char smr[];
    const uint32_t sbase = (uint32_t)__cvta_generic_to_shared(smr);
    const int tid = threadIdx.x;
    const int wid = tid >> 5, lane = tid & 31;
    const int qw = wid >> 1, nw = wid & 1;
    const int m0 = blockIdx.x * 64;

    float acc[8][4];
#pragma unroll
    for (int i = 0; i < 8; ++i)
#pragma unroll
        for (int j = 0; j < 4; ++j) acc[i][j] = 0.f;

#pragma unroll
    for (int kb = 0; kb < KA / 64; ++kb) {
        __syncthreads();
#pragma unroll
        for (int i = 0; i < 2; ++i) {
            int idx = tid + i * 256;
            int r = idx >> 3, c = idx & 7;
            size_t go = (size_t)(m0 + r) * KA + kb * 64 + c * 8;
            *reinterpret_cast<uint4*>(smr + GOAH + (r * 72 + c * 8) * 2) =
                *reinterpret_cast<const uint4*>(Ahg + go);
            *reinterpret_cast<uint4*>(smr + GOAL + (r * 72 + c * 8) * 2) =
                *reinterpret_cast<const uint4*>(Alg + go);
        }
#pragma unroll
        for (int i = 0; i < 4; ++i) {
            int idx = tid + i * 256;
            int r = idx >> 4, c = idx & 15;
            size_t go = (size_t)(kb * 64 + r) * 128 + c * 8;
            *reinterpret_cast<uint4*>(smr + GOBH + (r * 136 + c * 8) * 2) =
                *reinterpret_cast<const uint4*>(Bhg + go);
            *reinterpret_cast<uint4*>(smr + GOBL + (r * 136 + c * 8) * 2) =
                *reinterpret_cast<const uint4*>(Blg + go);
        }
        __syncthreads();
        mma_tile64(sbase, qw, nw, lane, acc);
    }

    const int g = lane >> 2, t = lane & 3;
    const int r0 = m0 + qw * 16 + g, r1 = r0 + 8;
#pragma unroll
    for (int nt = 0; nt < 8; ++nt) {
        int col = nw * 64 + nt * 8 + 2 * t;
        if (SPLIT) {
            uint32_t h, l;
            split2(acc[nt][0], acc[nt][1], h, l);
            *reinterpret_cast<uint32_t*>(Ch + (size_t)r0 * 128 + col) = h;
            *reinterpret_cast<uint32_t*>(Cl + (size_t)r0 * 128 + col) = l;
            split2(acc[nt][2], acc[nt][3], h, l);
            *reinterpret_cast<uint32_t*>(Ch + (size_t)r1 * 128 + col) = h;
            *reinterpret_cast<uint32_t*>(Cl + (size_t)r1 * 128 + col) = l;
        } else {
            float2 v0 = {acc[nt][0], acc[nt][1]};
            float2 v1 = {acc[nt][2], acc[nt][3]};
            *reinterpret_cast<float2*>(Cf + (size_t)r0 * 128 + col) = v0;
            *reinterpret_cast<float2*>(Cf + (size_t)r1 * 128 + col) = v1;
        }
    }
}

// ======================================================================
// Flash attention v2: 128 q-rows/block, warp-private softmax,
// Q register-resident, cp.async double-buffered K/V.
// grid = (NQB/128, NBATCH), 256 threads.
// ======================================================================
// stage layout (bf16, rows padded to 136): KH KL VH VL, 17408 B each
#define STG   17408
#define SSTAGE (4 * STG)          // 69632 per stage
#define ASMSZ2 (2 * SSTAGE)       // 139264

__global__ __launch_bounds__(256, 1) void k_attn()
{
    extern __shared__ char smr[];
    const uint32_t sbase = (uint32_t)__cvta_generic_to_shared(smr);

    const int tid  = threadIdx.x;
    const int w    = tid >> 5, lane = tid & 31;
    const int g    = lane >> 2, t = lane & 3;
    const int b    = blockIdx.y;
    const size_t qrow0 = (size_t)b * NQB + blockIdx.x * 128;

    const int rA = lane & 15;
    const int cA = (lane >> 4) * 8;
    const int rB = ((lane >> 3) & 2) * 4 + (lane & 7);
    const int cB = ((lane >> 3) & 1) * 8;
    const int rV = ((lane >> 3) & 1) * 8 + (lane & 7);
    const int cV = ((lane >> 3) & 2) * 4;

    // ---- stage Q (hi at smem 0, lo at 34816), load A-fragments, free smem ----
    uint32_t Qh[8][4], Ql[8][4];
    {
        const __nv_bfloat16* qh = g_qh + qrow0 * 128;
        const __nv_bfloat16* ql = g_ql + qrow0 * 128;
#pragma unroll
        for (int i = 0; i < 8; ++i) {
            int idx = tid + i * 256;            // 0..2047
            int r = idx >> 4, c = idx & 15;
            uint32_t so = (uint32_t)(r * 136 + c * 8) * 2;
            cpa16(sbase + so,         qh + (size_t)r * 128 + c * 8);
            cpa16(sbase + 34816 + so, ql + (size_t)r * 128 + c * 8);
        }
        cpa_commit();
        asm volatile("cp.async.wait_group 0;");
        __syncthreads();
#pragma unroll
        for (int ch = 0; ch < 8; ++ch) {
            uint32_t Aaddr = sbase + (uint32_t)((w * 16 + rA) * 136 + ch * 16 + cA) * 2;
            ldsm4(Qh[ch], Aaddr);
            ldsm4(Ql[ch], Aaddr + 34816);
        }
        __syncthreads();
    }

    float O[16][4];
#pragma unroll
    for (int i = 0; i < 16; ++i)
#pragma unroll
        for (int j = 0; j < 4; ++j) O[i][j] = 0.f;
    float m0r = -1e30f, m1r = -1e30f, l0 = 0.f, l1 = 0.f;

    const size_t kvbase = (size_t)b * NKB * 128;
    // prefetch helper (macro-ish lambda): stage s, tile jt
    auto prefetch = [&](int jt, int s) {
        size_t base = kvbase + (size_t)jt * 64 * 128;
        uint32_t sb = sbase + s * SSTAGE;
#pragma unroll
        for (int i = 0; i < 16; ++i) {
            int arr = i >> 2;
            int idx = tid + (i & 3) * 256;      // 0..1023
            int r = idx >> 4, c = idx & 15;
            uint32_t so = sb + arr * STG + (uint32_t)(r * 136 + c * 8) * 2;
            const __nv_bfloat16* src;
            if      (arr == 0) src = g_kh + base + (size_t)r * 128 + c * 8;
            else if (arr == 1) src = g_kl + base + (size_t)r * 128 + c * 8;
            else if (arr == 2) src = g_vh + base + (size_t)r * 128 + c * 8;
            else               src = g_vl + base + (size_t)r * 128 + c * 8;
            cpa16(so, src);
        }
        cpa_commit();
    };

    prefetch(0, 0);

    const int NIT = NKB / 64;
    for (int jt = 0; jt < NIT; ++jt) {
        const int s = jt & 1;
        if (jt + 1 < NIT) {
            prefetch(jt + 1, s ^ 1);
            asm volatile("cp.async.wait_group 1;");
        } else {
            asm volatile("cp.async.wait_group 0;");
        }
        __syncthreads();

        const uint32_t KHb = sbase + s * SSTAGE;
        const uint32_t KLb = KHb + STG;
        const uint32_t VHb = KHb + 2 * STG;
        const uint32_t VLb = KHb + 3 * STG;

        // ---- S = Q K^T ----
        float sA[8][4];
#pragma unroll
        for (int i = 0; i < 8; ++i)
#pragma unroll
            for (int j = 0; j < 4; ++j) sA[i][j] = 0.f;

#pragma unroll
        for (int ch = 0; ch < 8; ++ch) {
            uint32_t col = (uint32_t)(ch * 16 + cB) * 2;
#pragma unroll
            for (int r4 = 0; r4 < 4; ++r4) {
                uint32_t ra = (uint32_t)((r4 * 16 + rB) * 136) * 2 + col;
                uint32_t bh[4], bl[4];
                ldsm4(bh, KHb + ra);
                ldsm4(bl, KLb + ra);
                float* s0 = sA[r4 * 2];
                float* s1 = sA[r4 * 2 + 1];
                mma16816(s0, Qh[ch], bh);      mma16816(s1, Qh[ch], bh + 2);
                mma16816(s0, Qh[ch], bl);      mma16816(s1, Qh[ch], bl + 2);
                mma16816(s0, Ql[ch], bh);      mma16816(s1, Ql[ch], bh + 2);
            }
        }

        // ---- warp-private online softmax (rows g and g+8 of this warp) ----
        float rm0 = sA[0][0], rm1 = sA[0][2];
#pragma unroll
        for (int nt = 0; nt < 8; ++nt) {
            rm0 = fmaxf(rm0, fmaxf(sA[nt][0], sA[nt][1]));
            rm1 = fmaxf(rm1, fmaxf(sA[nt][2], sA[nt][3]));
        }
        rm0 = fmaxf(rm0, __shfl_xor_sync(0xffffffffu, rm0, 1));
        rm0 = fmaxf(rm0, __shfl_xor_sync(0xffffffffu, rm0, 2));
        rm1 = fmaxf(rm1, __shfl_xor_sync(0xffffffffu, rm1, 1));
        rm1 = fmaxf(rm1, __shfl_xor_sync(0xffffffffu, rm1, 2));
        float mn0 = fmaxf(m0r, rm0);
        float mn1 = fmaxf(m1r, rm1);
        float sc0 = __expf(m0r - mn0);
        float sc1 = __expf(m1r - mn1);

        float p[8][4];
        float ls0 = 0.f, ls1 = 0.f;
#pragma unroll
        for (int nt = 0; nt < 8; ++nt) {
            p[nt][0] = __expf(sA[nt][0] - mn0);
            p[nt][1] = __expf(sA[nt][1] - mn0);
            p[nt][2] = __expf(sA[nt][2] - mn1);
            p[nt][3] = __expf(sA[nt][3] - mn1);
            ls0 += p[nt][0] + p[nt][1];
            ls1 += p[nt][2] + p[nt][3];
        }
        ls0 += __shfl_xor_sync(0xffffffffu, ls0, 1);
        ls0 += __shfl_xor_sync(0xffffffffu, ls0, 2);
        ls1 += __shfl_xor_sync(0xffffffffu, ls1, 1);
        ls1 += __shfl_xor_sync(0xffffffffu, ls1, 2);
        l0 = l0 * sc0 + ls0;
        l1 = l1 * sc1 + ls1;
        m0r = mn0; m1r = mn1;

#pragma unroll
        for (int nt = 0; nt < 16; ++nt) {
            O[nt][0] *= sc0; O[nt][1] *= sc0;
            O[nt][2] *= sc1; O[nt][3] *= sc1;
        }

        // ---- P (split bf16) A-fragments: 4 kv-chunks of 16 ----
        uint32_t Ph[4][4], Pl[4][4];
#pragma unroll
        for (int c = 0; c < 4; ++c) {
            split2(p[2 * c][0],     p[2 * c][1],     Ph[c][0], Pl[c][0]);
            split2(p[2 * c][2],     p[2 * c][3],     Ph[c][1], Pl[c][1]);
            split2(p[2 * c + 1][0], p[2 * c + 1][1], Ph[c][2], Pl[c][2]);
            split2(p[2 * c + 1][2], p[2 * c + 1][3], Ph[c][3], Pl[c][3]);
        }

        // ---- O += P V ----
#pragma unroll
        for (int kc = 0; kc < 4; ++kc) {
#pragma unroll
            for (int dp = 0; dp < 8; ++dp) {
                uint32_t ra = (uint32_t)((kc * 16 + rV) * 136 + dp * 16 + cV) * 2;
                uint32_t vh[4], vl[4];
                ldsm4t(vh, VHb + ra);
                ldsm4t(vl, VLb + ra);
                float* o0 = O[dp * 2];
                float* o1 = O[dp * 2 + 1];
                mma16816(o0, Ph[kc], vh);      mma16816(o1, Ph[kc], vh + 2);
                mma16816(o0, Ph[kc], vl);      mma16816(o1, Ph[kc], vl + 2);
                mma16816(o0, Pl[kc], vh);      mma16816(o1, Pl[kc], vh + 2);
            }
        }
        __syncthreads();
    }

    // ---- epilogue: normalize, split, store (warp-private rows) ----
    float inv0 = 1.f / l0, inv1 = 1.f / l1;
    size_t out0 = (qrow0 + w * 16 + g) * 128;
    size_t out1 = (qrow0 + w * 16 + g + 8) * 128;
#pragma unroll
    for (int nt = 0; nt < 16; ++nt) {
        int c0 = nt * 8 + 2 * t;
        uint32_t h, l;
        split2(O[nt][0] * inv0, O[nt][1] * inv0, h, l);
        *reinterpret_cast<uint32_t*>(g_xrh + out0 + c0) = h;
        *reinterpret_cast<uint32_t*>(g_xrl + out0 + c0) = l;
        split2(O[nt][2] * inv1, O[nt][3] * inv1, h, l);
        *reinterpret_cast<uint32_t*>(g_xrh + out1 + c0) = h;
        *reinterpret_cast<uint32_t*>(g_xrl + out1 + c0) = l;
    }
}

// ======================================================================
// BN stats + epilogue
// ======================================================================
__global__ void k_colstats()
{
    int f = threadIdx.x;
    const float* base = g_t + (size_t)blockIdx.x * 64 * 128;
    float s = 0.f, q = 0.f;
#pragma unroll 8
    for (int r = 0; r < 64; ++r) {
        float v = base[r * 128 + f];
        s += v; q += v * v;
    }
    g_psum[blockIdx.x * 128 + f] = s;
    g_psq [blockIdx.x * 128 + f] = q;
}

__global__ void k_stats()
{
    int f = threadIdx.x;
    float s = 0.f, q = 0.f;
    for (int b = 0; b < NQ / 64; ++b) {
        s += g_psum[b * 128 + f];
        q += g_psq [b * 128 + f];
    }
    float mean = s * (1.f / NQ);
    float var  = q * (1.f / NQ) - mean * mean;
    g_mean[f] = mean;
    g_rstd[f] = rsqrtf(var + BN_EPS);
}

__global__ void k_final(const float* __restrict__ gamma, const float* __restrict__ beta,
                        float* __restrict__ out)
{
    int idx = blockIdx.x * 256 + threadIdx.x;
    int f   = (idx & 31) * 4;
    float4 tv = *reinterpret_cast<const float4*>(g_t    + (size_t)idx * 4);
    float4 xd = *reinterpret_cast<const float4*>(g_xdec + (size_t)idx * 4);
    float4 r;
    r.x = xd.x + (tv.x - g_mean[f + 0]) * g_rstd[f + 0] * gamma[f + 0] + beta[f + 0];
    r.y = xd.y + (tv.y - g_mean[f + 1]) * g_rstd[f + 1] * gamma[f + 1] + beta[f + 1];
    r.z = xd.z + (tv.z - g_mean[f + 2]) * g_rstd[f + 2] * gamma[f + 2] + beta[f + 2];
    r.w = xd.w + (tv.w - g_mean[f + 3]) * g_rstd[f + 3] * gamma[f + 3] + beta[f + 3];
    *reinterpret_cast<float4*>(out + (size_t)idx * 4) = r;
}

// ======================================================================
extern "C" void kernel_launch(void* const* d_in, const int* in_sizes, int n_in,
                              void* d_out, int out_size)
{
    const float* xdec_f = (const float*)d_in[0];
    const float* xenc_f = (const float*)d_in[1];
    const int*   nbr    = (const int*)  d_in[2];
    const float* Wp1    = (const float*)d_in[3];
    const float* Wq     = (const float*)d_in[4];
    const float* Wk     = (const float*)d_in[5];
    const float* Wv     = (const float*)d_in[6];
    const float* Wt     = (const float*)d_in[7];
    const float* gamma  = (const float*)d_in[8];
    const float* beta   = (const float*)d_in[9];
    float* out = (float*)d_out;

    __nv_bfloat16 *p_eh, *p_el, *p_xdh, *p_xdl, *p_xrh, *p_xrl;
    __nv_bfloat16 *p_wkh, *p_wkl, *p_wvh, *p_wvl, *p_wqh, *p_wql, *p_wth, *p_wtl;
    __nv_bfloat16 *p_qh, *p_ql, *p_kh, *p_kl, *p_vh, *p_vl;
    float *p_t;
    cudaGetSymbolAddress((void**)&p_eh,  g_eh);   cudaGetSymbolAddress((void**)&p_el,  g_el);
    cudaGetSymbolAddress((void**)&p_xdh, g_xdh);  cudaGetSymbolAddress((void**)&p_xdl, g_xdl);
    cudaGetSymbolAddress((void**)&p_xrh, g_xrh);  cudaGetSymbolAddress((void**)&p_xrl, g_xrl);
    cudaGetSymbolAddress((void**)&p_wkh, g_wkh);  cudaGetSymbolAddress((void**)&p_wkl, g_wkl);
    cudaGetSymbolAddress((void**)&p_wvh, g_wvh);  cudaGetSymbolAddress((void**)&p_wvl, g_wvl);
    cudaGetSymbolAddress((void**)&p_wqh, g_wqh);  cudaGetSymbolAddress((void**)&p_wql, g_wql);
    cudaGetSymbolAddress((void**)&p_wth, g_wth);  cudaGetSymbolAddress((void**)&p_wtl, g_wtl);
    cudaGetSymbolAddress((void**)&p_qh,  g_qh);   cudaGetSymbolAddress((void**)&p_ql,  g_ql);
    cudaGetSymbolAddress((void**)&p_kh,  g_kh);   cudaGetSymbolAddress((void**)&p_kl,  g_kl);
    cudaGetSymbolAddress((void**)&p_vh,  g_vh);   cudaGetSymbolAddress((void**)&p_vl,  g_vl);
    cudaGetSymbolAddress((void**)&p_t,   g_t);

    cudaFuncSetAttribute(k_p1_mma,          cudaFuncAttributeMaxDynamicSharedMemorySize, GSMSZ);
    cudaFuncSetAttribute(k_proj<64,  true>, cudaFuncAttributeMaxDynamicSharedMemorySize, GSMSZ);
    cudaFuncSetAttribute(k_proj<128, true>, cudaFuncAttributeMaxDynamicSharedMemorySize, GSMSZ);
    cudaFuncSetAttribute(k_proj<128, false>,cudaFuncAttributeMaxDynamicSharedMemorySize, GSMSZ);
    cudaFuncSetAttribute(k_attn,            cudaFuncAttributeMaxDynamicSharedMemorySize, ASMSZ2);

    k_split7<<<SB6 / 1024, 256>>>(xdec_f, xenc_f, Wp1, Wk, Wv, Wq, Wt);
    k_p1_mma<<<NQ / 64, 256, GSMSZ>>>(nbr);
    k_proj<64,  true><<<NKV / 64, 256, GSMSZ>>>(p_eh, p_el, p_wkh, p_wkl, p_kh, p_kl, nullptr);
    k_proj<64,  true><<<NKV / 64, 256, GSMSZ>>>(p_eh, p_el, p_wvh, p_wvl, p_vh, p_vl, nullptr);
    k_proj<128, true><<<NQ / 64, 256, GSMSZ>>>(p_xdh, p_xdl, p_wqh, p_wql, p_qh, p_ql, nullptr);
    k_attn<<<dim3(NQB / 128, NBATCH), 256, ASMSZ2>>>();
    k_proj<128, false><<<NQ / 64, 256, GSMSZ>>>(p_xrh, p_xrl, p_wth, p_wtl, nullptr, nullptr, p_t);
    k_colstats<<<NQ / 64, 128>>>();
    k_stats<<<1, 128>>>();
    k_final<<<(NQ * NF / 4) / 256, 256>>>(gamma, beta, out);
}

// round 7
// speedup vs baseline: 4.2683x; 1.0101x over previous
#include <cuda_runtime.h>
#include <cuda_bf16.h>
#include <cstdint>

#define NQ      16384
#define NKV     32768
#define DEC     64
#define NF      128
#define NBATCH  8
#define NQB     2048
#define NKB     4096
#define BN_EPS  1e-4f

// ---------------- scratch (alloc-free: device globals) ----------------
__device__ float g_xdec[NQ * NF];
__device__ float g_t   [NQ * NF];
__device__ float g_psum[(NQ / 64) * NF];
__device__ float g_psq [(NQ / 64) * NF];
__device__ float g_mean[NF];
__device__ float g_rstd[NF];
__device__ __nv_bfloat16 g_dfh[NQ * DEC],  g_dfl[NQ * DEC];
__device__ __nv_bfloat16 g_eh [NKV * DEC], g_el [NKV * DEC];
__device__ __nv_bfloat16 g_wp1h[27 * 64 * 128], g_wp1l[27 * 64 * 128];
__device__ __nv_bfloat16 g_wkh[64 * 128],  g_wkl[64 * 128];
__device__ __nv_bfloat16 g_wvh[64 * 128],  g_wvl[64 * 128];
__device__ __nv_bfloat16 g_wqh[128 * 128], g_wql[128 * 128];
__device__ __nv_bfloat16 g_wth[128 * 128], g_wtl[128 * 128];
__device__ __nv_bfloat16 g_xdh[NQ * NF],  g_xdl[NQ * NF];
__device__ __nv_bfloat16 g_qh[NQ * NF],   g_ql[NQ * NF];
__device__ __nv_bfloat16 g_kh[NKV * NF],  g_kl[NKV * NF];
__device__ __nv_bfloat16 g_vh[NKV * NF],  g_vl[NKV * NF];
__device__ __nv_bfloat16 g_xrh[NQ * NF],  g_xrl[NQ * NF];

// ---------------- helpers ----------------
__device__ __forceinline__ uint32_t packb(__nv_bfloat16 x, __nv_bfloat16 y) {
    __nv_bfloat162 v(x, y);
    return *reinterpret_cast<uint32_t*>(&v);
}
__device__ __forceinline__ void split2(float a, float b, uint32_t& hi, uint32_t& lo) {
    __nv_bfloat16 ah = __float2bfloat16(a);
    __nv_bfloat16 bh = __float2bfloat16(b);
    float ar = a - __bfloat162float(ah);
    float br = b - __bfloat162float(bh);
    hi = packb(ah, bh);
    lo = packb(__float2bfloat16(ar), __float2bfloat16(br));
}
__device__ __forceinline__ void mma16816(float* d, const uint32_t* a, const uint32_t* b) {
    asm volatile("mma.sync.aligned.m16n8k16.row.col.f32.bf16.bf16.f32 "
                 "{%0,%1,%2,%3}, {%4,%5,%6,%7}, {%8,%9}, {%0,%1,%2,%3};"
                 : "+f"(d[0]), "+f"(d[1]), "+f"(d[2]), "+f"(d[3])
                 : "r"(a[0]), "r"(a[1]), "r"(a[2]), "r"(a[3]), "r"(b[0]), "r"(b[1]));
}
__device__ __forceinline__ void ldsm4(uint32_t* r, uint32_t addr) {
    asm volatile("ldmatrix.sync.aligned.m8n8.x4.shared.b16 {%0,%1,%2,%3}, [%4];"
                 : "=r"(r[0]), "=r"(r[1]), "=r"(r[2]), "=r"(r[3]) : "r"(addr));
}
__device__ __forceinline__ void ldsm4t(uint32_t* r, uint32_t addr) {
    asm volatile("ldmatrix.sync.aligned.m8n8.x4.trans.shared.b16 {%0,%1,%2,%3}, [%4];"
                 : "=r"(r[0]), "=r"(r[1]), "=r"(r[2]), "=r"(r[3]) : "r"(addr));
}
__device__ __forceinline__ void cpa16(uint32_t dst, const void* src) {
    asm volatile("cp.async.cg.shared.global [%0], [%1], 16;" :: "r"(dst), "l"(src));
}
__device__ __forceinline__ void cpa_commit() {
    asm volatile("cp.async.commit_group;");
}

// ======================================================================
// Split-prep
// ======================================================================
#define SB0 (NQ * DEC)
#define SB1 (SB0 + NKV * DEC)
#define SB2 (SB1 + 27 * 64 * 128)
#define SB3 (SB2 + 64 * 128)
#define SB4 (SB3 + 64 * 128)
#define SB5 (SB4 + 128 * 128)
#define SB6 (SB5 + 128 * 128)

__device__ __forceinline__ void split4(float4 v, uint2& h, uint2& l) {
    uint32_t h0, l0, h1, l1;
    split2(v.x, v.y, h0, l0);
    split2(v.z, v.w, h1, l1);
    h = {h0, h1};
    l = {l0, l1};
}

__global__ void k_split7(const float* __restrict__ xdf, const float* __restrict__ xef,
                         const float* __restrict__ Wp1, const float* __restrict__ Wk,
                         const float* __restrict__ Wv,  const float* __restrict__ Wq,
                         const float* __restrict__ Wt)
{
    int e = (blockIdx.x * 256 + threadIdx.x) * 4;
    const float* src; __nv_bfloat16 *dh, *dl; int off;
    if      (e < SB0) { src = xdf; dh = g_dfh;  dl = g_dfl;  off = e; }
    else if (e < SB1) { src = xef; dh = g_eh;   dl = g_el;   off = e - SB0; }
    else if (e < SB2) { src = Wp1; dh = g_wp1h; dl = g_wp1l; off = e - SB1; }
    else if (e < SB3) { src = Wk;  dh = g_wkh;  dl = g_wkl;  off = e - SB2; }
    else if (e < SB4) { src = Wv;  dh = g_wvh;  dl = g_wvl;  off = e - SB3; }
    else if (e < SB5) { src = Wq;  dh = g_wqh;  dl = g_wql;  off = e - SB4; }
    else              { src = Wt;  dh = g_wth;  dl = g_wtl;  off = e - SB5; }
    float4 v = *reinterpret_cast<const float4*>(src + off);
    uint2 h, l;
    split4(v, h, l);
    *reinterpret_cast<uint2*>(dh + off) = h;
    *reinterpret_cast<uint2*>(dl + off) = l;
}

// ======================================================================
// Shared MMA-tile machinery (64x128 tile, 8 warps as 4 qw x 2 nw)
// A tiles: [64][72] bf16; B tiles: [64][136] bf16
// ======================================================================
#define GOAH  0
#define GOAL  9216
#define GOBH  18432
#define GOBL  35840
#define GSTG  53248            // one full A+B stage (p1 double buffer)
#define GSMSZ (GSTG + 4096)    // generic GEMM smem (stats scratch tail)

__device__ __forceinline__ void mma_tile64(uint32_t sbase,
                                           uint32_t bOffH, uint32_t bOffL,
                                           int qw, int nw, int lane,
                                           float acc[8][4])
{
    const int rA = lane & 15, cA = (lane >> 4) * 8;
    const int rV = ((lane >> 3) & 1) * 8 + (lane & 7);
    const int cV = ((lane >> 3) & 2) * 4;
#pragma unroll
    for (int kc = 0; kc < 4; ++kc) {
        uint32_t Aaddr = sbase + (uint32_t)((qw * 16 + rA) * 72 + kc * 16 + cA) * 2;
        uint32_t Ah4[4], Al4[4];
        ldsm4(Ah4, Aaddr + GOAH);
        ldsm4(Al4, Aaddr + GOAL);
#pragma unroll
        for (int nt2 = 0; nt2 < 4; ++nt2) {
            uint32_t ra = (uint32_t)((kc * 16 + rV) * 136 + nw * 64 + nt2 * 16 + cV) * 2;
            uint32_t Bh4[4], Bl4[4];
            ldsm4t(Bh4, sbase + bOffH + ra);
            ldsm4t(Bl4, sbase + bOffL + ra);
            float* a0 = acc[nt2 * 2];
            float* a1 = acc[nt2 * 2 + 1];
            mma16816(a0, Ah4, Bh4);  mma16816(a1, Ah4, Bh4 + 2);
            mma16816(a0, Ah4, Bl4);  mma16816(a1, Ah4, Bl4 + 2);
            mma16816(a0, Al4, Bh4);  mma16816(a1, Al4, Bh4 + 2);
        }
    }
}

// ======================================================================
// p1 gather-conv, cp.async double-buffered over the 27 taps
// ======================================================================
__global__ __launch_bounds__(256) void k_p1_mma(const int* __restrict__ nbr)
{
    extern __shared__ char smr[];
    const uint32_t sbase = (uint32_t)__cvta_generic_to_shared(smr);
    const int tid = threadIdx.x;
    const int wid = tid >> 5, lane = tid & 31;
    const int qw = wid >> 1, nw = wid & 1;
    const int m0 = blockIdx.x * 64;

    float acc[8][4];
#pragma unroll
    for (int i = 0; i < 8; ++i)
#pragma unroll
        for (int j = 0; j < 4; ++j) acc[i][j] = 0.f;

    auto prefetch = [&](int k, int s) {
        uint32_t sb = sbase + s * GSTG;
#pragma unroll
        for (int i = 0; i < 2; ++i) {
            int idx = tid + i * 256;          // 0..511
            int r = idx >> 3, c = idx & 7;
            int gi = nbr[(m0 + r) * 27 + k];
            uint32_t so = (uint32_t)(r * 72 + c * 8) * 2;
            cpa16(sb + GOAH + so, g_dfh + (size_t)gi * DEC + c * 8);
            cpa16(sb + GOAL + so, g_dfl + (size_t)gi * DEC + c * 8);
        }
        const __nv_bfloat16* wh = g_wp1h + (size_t)k * 64 * 128;
        const __nv_bfloat16* wl = g_wp1l + (size_t)k * 64 * 128;
#pragma unroll
        for (int i = 0; i < 4; ++i) {
            int idx = tid + i * 256;          // 0..1023
            int r = idx >> 4, c = idx & 15;
            uint32_t so = (uint32_t)(r * 136 + c * 8) * 2;
            cpa16(sb + GOBH + so, wh + r * 128 + c * 8);
            cpa16(sb + GOBL + so, wl + r * 128 + c * 8);
        }
        cpa_commit();
    };

    prefetch(0, 0);
    for (int k = 0; k < 27; ++k) {
        const int s = k & 1;
        if (k + 1 < 27) {
            prefetch(k + 1, s ^ 1);
            asm volatile("cp.async.wait_group 1;");
        } else {
            asm volatile("cp.async.wait_group 0;");
        }
        __syncthreads();
        mma_tile64(sbase + s * GSTG, GOBH, GOBL, qw, nw, lane, acc);
        __syncthreads();
    }

    const int g = lane >> 2, t = lane & 3;
    const int r0 = m0 + qw * 16 + g, r1 = r0 + 8;
#pragma unroll
    for (int nt = 0; nt < 8; ++nt) {
        int col = nw * 64 + nt * 8 + 2 * t;
        float2 v0 = {acc[nt][0], acc[nt][1]};
        float2 v1 = {acc[nt][2], acc[nt][3]};
        *reinterpret_cast<float2*>(g_xdec + (size_t)r0 * 128 + col) = v0;
        *reinterpret_cast<float2*>(g_xdec + (size_t)r1 * 128 + col) = v1;
        uint32_t h, l;
        split2(v0.x, v0.y, h, l);
        *reinterpret_cast<uint32_t*>(g_xdh + (size_t)r0 * 128 + col) = h;
        *reinterpret_cast<uint32_t*>(g_xdl + (size_t)r0 * 128 + col) = l;
        split2(v1.x, v1.y, h, l);
        *reinterpret_cast<uint32_t*>(g_xdh + (size_t)r1 * 128 + col) = h;
        *reinterpret_cast<uint32_t*>(g_xdl + (size_t)r1 * 128 + col) = l;
    }
}

// ======================================================================
// Fused K+V projection: enc A-tile loaded once, two B sets, two accums
// smem: A(18432) + Bk(34816) + Bv(34816) = 88064
// ======================================================================
#define KV_BKH 18432
#define KV_BKL (KV_BKH + 17408)
#define KV_BVH (KV_BKH + 34816)
#define KV_BVL (KV_BVH + 17408)
#define KVSMSZ (KV_BVH + 34816)

__global__ __launch_bounds__(256) void k_projKV()
{
    extern __shared__ char smr[];
    const uint32_t sbase = (uint32_t)__cvta_generic_to_shared(smr);
    const int tid = threadIdx.x;
    const int wid = tid >> 5, lane = tid & 31;
    const int qw = wid >> 1, nw = wid & 1;
    const int m0 = blockIdx.x * 64;

#pragma unroll
    for (int i = 0; i < 2; ++i) {
        int idx = tid + i * 256;
        int r = idx >> 3, c = idx & 7;
        size_t go = (size_t)(m0 + r) * DEC + c * 8;
        uint32_t so = (uint32_t)(r * 72 + c * 8) * 2;
        cpa16(sbase + GOAH + so, g_eh + go);
        cpa16(sbase + GOAL + so, g_el + go);
    }
#pragma unroll
    for (int i = 0; i < 4; ++i) {
        int idx = tid + i * 256;
        int r = idx >> 4, c = idx & 15;
        size_t go = (size_t)r * 128 + c * 8;
        uint32_t so = (uint32_t)(r * 136 + c * 8) * 2;
        cpa16(sbase + KV_BKH + so, g_wkh + go);
        cpa16(sbase + KV_BKL + so, g_wkl + go);
        cpa16(sbase + KV_BVH + so, g_wvh + go);
        cpa16(sbase + KV_BVL + so, g_wvl + go);
    }
    cpa_commit();
    asm volatile("cp.async.wait_group 0;");
    __syncthreads();

    float accK[8][4], accV[8][4];
#pragma unroll
    for (int i = 0; i < 8; ++i)
#pragma unroll
        for (int j = 0; j < 4; ++j) { accK[i][j] = 0.f; accV[i][j] = 0.f; }

    mma_tile64(sbase, KV_BKH, KV_BKL, qw, nw, lane, accK);
    mma_tile64(sbase, KV_BVH, KV_BVL, qw, nw, lane, accV);

    const int g = lane >> 2, t = lane & 3;
    const int r0 = m0 + qw * 16 + g, r1 = r0 + 8;
#pragma unroll
    for (int nt = 0; nt < 8; ++nt) {
        int col = nw * 64 + nt * 8 + 2 * t;
        uint32_t h, l;
        split2(accK[nt][0], accK[nt][1], h, l);
        *reinterpret_cast<uint32_t*>(g_kh + (size_t)r0 * 128 + col) = h;
        *reinterpret_cast<uint32_t*>(g_kl + (size_t)r0 * 128 + col) = l;
        split2(accK[nt][2], accK[nt][3], h, l);
        *reinterpret_cast<uint32_t*>(g_kh + (size_t)r1 * 128 + col) = h;
        *reinterpret_cast<uint32_t*>(g_kl + (size_t)r1 * 128 + col) = l;
        split2(accV[nt][0], accV[nt][1], h, l);
        *reinterpret_cast<uint32_t*>(g_vh + (size_t)r0 * 128 + col) = h;
        *reinterpret_cast<uint32_t*>(g_vl + (size_t)r0 * 128 + col) = l;
        split2(accV[nt][2], accV[nt][3], h, l);
        *reinterpret_cast<uint32_t*>(g_vh + (size_t)r1 * 128 + col) = h;
        *reinterpret_cast<uint32_t*>(g_vl + (size_t)r1 * 128 + col) = l;
    }
}

// ======================================================================
// Generic split-bf16 MMA GEMM (+ optional split output, + optional BN stats)
// ======================================================================
template <int KA, bool SPLIT, bool STATS>
__global__ __launch_bounds__(256) void k_proj(const __nv_bfloat16* __restrict__ Ahg,
                                              const __nv_bfloat16* __restrict__ Alg,
                                              const __nv_bfloat16* __restrict__ Bhg,
                                              const __nv_bfloat16* __restrict__ Blg,
                                              __nv_bfloat16* __restrict__ Ch,
                                              __nv_bfloat16* __restrict__ Cl,
                                              float* __restrict__ Cf)
{
    extern __shared__ char smr[];
    const uint32_t sbase = (uint32_t)__cvta_generic_to_shared(smr);
    const int tid = threadIdx.x;
    const int wid = tid >> 5, lane = tid & 31;
    const int qw = wid >> 1, nw = wid & 1;
    const int m0 = blockIdx.x * 64;

    float acc[8][4];
#pragma unroll
    for (int i = 0; i < 8; ++i)
#pragma unroll
        for (int j = 0; j < 4; ++j) acc[i][j] = 0.f;

#pragma unroll
    for (int kb = 0; kb < KA / 64; ++kb) {
        __syncthreads();
#pragma unroll
        for (int i = 0; i < 2; ++i) {
            int idx = tid + i * 256;
            int r = idx >> 3, c = idx & 7;
            size_t go = (size_t)(m0 + r) * KA + kb * 64 + c * 8;
            uint32_t so = (uint32_t)(r * 72 + c * 8) * 2;
            cpa16(sbase + GOAH + so, Ahg + go);
            cpa16(sbase + GOAL + so, Alg + go);
        }
#pragma unroll
        for (int i = 0; i < 4; ++i) {
            int idx = tid + i * 256;
            int r = idx >> 4, c = idx & 15;
            size_t go = (size_t)(kb * 64 + r) * 128 + c * 8;
            uint32_t so = (uint32_t)(r * 136 + c * 8) * 2;
            cpa16(sbase + GOBH + so, Bhg + go);
            cpa16(sbase + GOBL + so, Blg + go);
        }
        cpa_commit();
        asm volatile("cp.async.wait_group 0;");
        __syncthreads();
        mma_tile64(sbase, GOBH, GOBL, qw, nw, lane, acc);
    }

    const int g = lane >> 2, t = lane & 3;
    const int r0 = m0 + qw * 16 + g, r1 = r0 + 8;
#pragma unroll
    for (int nt = 0; nt < 8; ++nt) {
        int col = nw * 64 + nt * 8 + 2 * t;
        if (SPLIT) {
            uint32_t h, l;
            split2(acc[nt][0], acc[nt][1], h, l);
            *reinterpret_cast<uint32_t*>(Ch + (size_t)r0 * 128 + col) = h;
            *reinterpret_cast<uint32_t*>(Cl + (size_t)r0 * 128 + col) = l;
            split2(acc[nt][2], acc[nt][3], h, l);
            *reinterpret_cast<uint32_t*>(Ch + (size_t)r1 * 128 + col) = h;
            *reinterpret_cast<uint32_t*>(Cl + (size_t)r1 * 128 + col) = l;
        } else {
            float2 v0 = {acc[nt][0], acc[nt][1]};
            float2 v1 = {acc[nt][2], acc[nt][3]};
            *reinterpret_cast<float2*>(Cf + (size_t)r0 * 128 + col) = v0;
            *reinterpret_cast<float2*>(Cf + (size_t)r1 * 128 + col) = v1;
        }
    }

    if (STATS) {
        // deterministic per-block column sums/sumsq of C
        float* sS = reinterpret_cast<float*>(smr);          // [4][128]
        float* sQ = reinterpret_cast<float*>(smr + 2048);   // [4][128]
        __syncthreads();
        float cs[8][2], cq[8][2];
#pragma unroll
        for (int nt = 0; nt < 8; ++nt) {
            cs[nt][0] = acc[nt][0] + acc[nt][2];
            cs[nt][1] = acc[nt][1] + acc[nt][3];
            cq[nt][0] = acc[nt][0] * acc[nt][0] + acc[nt][2] * acc[nt][2];
            cq[nt][1] = acc[nt][1] * acc[nt][1] + acc[nt][3] * acc[nt][3];
        }
        // reduce over g (lane bits 2..4), t stays fixed
#pragma unroll
        for (int off = 4; off < 32; off <<= 1) {
#pragma unroll
            for (int nt = 0; nt < 8; ++nt) {
                cs[nt][0] += __shfl_xor_sync(0xffffffffu, cs[nt][0], off);
                cs[nt][1] += __shfl_xor_sync(0xffffffffu, cs[nt][1], off);
                cq[nt][0] += __shfl_xor_sync(0xffffffffu, cq[nt][0], off);
                cq[nt][1] += __shfl_xor_sync(0xffffffffu, cq[nt][1], off);
            }
        }
        if (lane < 4) {
#pragma unroll
            for (int nt = 0; nt < 8; ++nt) {
                int col = nw * 64 + nt * 8 + 2 * lane;
                sS[qw * 128 + col]     = cs[nt][0];
                sS[qw * 128 + col + 1] = cs[nt][1];
                sQ[qw * 128 + col]     = cq[nt][0];
                sQ[qw * 128 + col + 1] = cq[nt][1];
            }
        }
        __syncthreads();
        if (tid < 128) {
            float s = sS[tid] + sS[128 + tid] + sS[256 + tid] + sS[384 + tid];
            float q = sQ[tid] + sQ[128 + tid] + sQ[256 + tid] + sQ[384 + tid];
            g_psum[blockIdx.x * 128 + tid] = s;
            g_psq [blockIdx.x * 128 + tid] = q;
        }
    }
}

// ======================================================================
// Flash attention (round-5 winner, unchanged)
// ======================================================================
#define STG   17408
#define SSTAGE (4 * STG)
#define ASMSZ2 (2 * SSTAGE)

__global__ __launch_bounds__(256, 1) void k_attn()
{
    extern __shared__ char smr[];
    const uint32_t sbase = (uint32_t)__cvta_generic_to_shared(smr);

    const int tid  = threadIdx.x;
    const int w    = tid >> 5, lane = tid & 31;
    const int g    = lane >> 2, t = lane & 3;
    const int b    = blockIdx.y;
    const size_t qrow0 = (size_t)b * NQB + blockIdx.x * 128;

    const int rA = lane & 15;
    const int cA = (lane >> 4) * 8;
    const int rB = ((lane >> 3) & 2) * 4 + (lane & 7);
    const int cB = ((lane >> 3) & 1) * 8;
    const int rV = ((lane >> 3) & 1) * 8 + (lane & 7);
    const int cV = ((lane >> 3) & 2) * 4;

    uint32_t Qh[8][4], Ql[8][4];
    {
        const __nv_bfloat16* qh = g_qh + qrow0 * 128;
        const __nv_bfloat16* ql = g_ql + qrow0 * 128;
#pragma unroll
        for (int i = 0; i < 8; ++i) {
            int idx = tid + i * 256;
            int r = idx >> 4, c = idx & 15;
            uint32_t so = (uint32_t)(r * 136 + c * 8) * 2;
            cpa16(sbase + so,         qh + (size_t)r * 128 + c * 8);
            cpa16(sbase + 34816 + so, ql + (size_t)r * 128 + c * 8);
        }
        cpa_commit();
        asm volatile("cp.async.wait_group 0;");
        __syncthreads();
#pragma unroll
        for (int ch = 0; ch < 8; ++ch) {
            uint32_t Aaddr = sbase + (uint32_t)((w * 16 + rA) * 136 + ch * 16 + cA) * 2;
            ldsm4(Qh[ch], Aaddr);
            ldsm4(Ql[ch], Aaddr + 34816);
        }
        __syncthreads();
    }

    float O[16][4];
#pragma unroll
    for (int i = 0; i < 16; ++i)
#pragma unroll
        for (int j = 0; j < 4; ++j) O[i][j] = 0.f;
    float m0r = -1e30f, m1r = -1e30f, l0 = 0.f, l1 = 0.f;

    const size_t kvbase = (size_t)b * NKB * 128;
    auto prefetch = [&](int jt, int s) {
        size_t base = kvbase + (size_t)jt * 64 * 128;
        uint32_t sb = sbase + s * SSTAGE;
#pragma unroll
        for (int i = 0; i < 16; ++i) {
            int arr = i >> 2;
            int idx = tid + (i & 3) * 256;
            int r = idx >> 4, c = idx & 15;
            uint32_t so = sb + arr * STG + (uint32_t)(r * 136 + c * 8) * 2;
            const __nv_bfloat16* src;
            if      (arr == 0) src = g_kh + base + (size_t)r * 128 + c * 8;
            else if (arr == 1) src = g_kl + base + (size_t)r * 128 + c * 8;
            else if (arr == 2) src = g_vh + base + (size_t)r * 128 + c * 8;
            else               src = g_vl + base + (size_t)r * 128 + c * 8;
            cpa16(so, src);
        }
        cpa_commit();
    };

    prefetch(0, 0);

    const int NIT = NKB / 64;
    for (int jt = 0; jt < NIT; ++jt) {
        const int s = jt & 1;
        if (jt + 1 < NIT) {
            prefetch(jt + 1, s ^ 1);
            asm volatile("cp.async.wait_group 1;");
        } else {
            asm volatile("cp.async.wait_group 0;");
        }
        __syncthreads();

        const uint32_t KHb = sbase + s * SSTAGE;
        const uint32_t KLb = KHb + STG;
        const uint32_t VHb = KHb + 2 * STG;
        const uint32_t VLb = KHb + 3 * STG;

        float sA[8][4];
#pragma unroll
        for (int i = 0; i < 8; ++i)
#pragma unroll
            for (int j = 0; j < 4; ++j) sA[i][j] = 0.f;

#pragma unroll
        for (int ch = 0; ch < 8; ++ch) {
            uint32_t col = (uint32_t)(ch * 16 + cB) * 2;
#pragma unroll
            for (int r4 = 0; r4 < 4; ++r4) {
                uint32_t ra = (uint32_t)((r4 * 16 + rB) * 136) * 2 + col;
                uint32_t bh[4], bl[4];
                ldsm4(bh, KHb + ra);
                ldsm4(bl, KLb + ra);
                float* s0 = sA[r4 * 2];
                float* s1 = sA[r4 * 2 + 1];
                mma16816(s0, Qh[ch], bh);      mma16816(s1, Qh[ch], bh + 2);
                mma16816(s0, Qh[ch], bl);      mma16816(s1, Qh[ch], bl + 2);
                mma16816(s0, Ql[ch], bh);      mma16816(s1, Ql[ch], bh + 2);
            }
        }

        float rm0 = sA[0][0], rm1 = sA[0][2];
#pragma unroll
        for (int nt = 0; nt < 8; ++nt) {
            rm0 = fmaxf(rm0, fmaxf(sA[nt][0], sA[nt][1]));
            rm1 = fmaxf(rm1, fmaxf(sA[nt][2], sA[nt][3]));
        }
        rm0 = fmaxf(rm0, __shfl_xor_sync(0xffffffffu, rm0, 1));
        rm0 = fmaxf(rm0, __shfl_xor_sync(0xffffffffu, rm0, 2));
        rm1 = fmaxf(rm1, __shfl_xor_sync(0xffffffffu, rm1, 1));
        rm1 = fmaxf(rm1, __shfl_xor_sync(0xffffffffu, rm1, 2));
        float mn0 = fmaxf(m0r, rm0);
        float mn1 = fmaxf(m1r, rm1);
        float sc0 = __expf(m0r - mn0);
        float sc1 = __expf(m1r - mn1);

        float p[8][4];
        float ls0 = 0.f, ls1 = 0.f;
#pragma unroll
        for (int nt = 0; nt < 8; ++nt) {
            p[nt][0] = __expf(sA[nt][0] - mn0);
            p[nt][1] = __expf(sA[nt][1] - mn0);
            p[nt][2] = __expf(sA[nt][2] - mn1);
            p[nt][3] = __expf(sA[nt][3] - mn1);
            ls0 += p[nt][0] + p[nt][1];
            ls1 += p[nt][2] + p[nt][3];
        }
        ls0 += __shfl_xor_sync(0xffffffffu, ls0, 1);
        ls0 += __shfl_xor_sync(0xffffffffu, ls0, 2);
        ls1 += __shfl_xor_sync(0xffffffffu, ls1, 1);
        ls1 += __shfl_xor_sync(0xffffffffu, ls1, 2);
        l0 = l0 * sc0 + ls0;
        l1 = l1 * sc1 + ls1;
        m0r = mn0; m1r = mn1;

#pragma unroll
        for (int nt = 0; nt < 16; ++nt) {
            O[nt][0] *= sc0; O[nt][1] *= sc0;
            O[nt][2] *= sc1; O[nt][3] *= sc1;
        }

        uint32_t Ph[4][4], Pl[4][4];
#pragma unroll
        for (int c = 0; c < 4; ++c) {
            split2(p[2 * c][0],     p[2 * c][1],     Ph[c][0], Pl[c][0]);
            split2(p[2 * c][2],     p[2 * c][3],     Ph[c][1], Pl[c][1]);
            split2(p[2 * c + 1][0], p[2 * c + 1][1], Ph[c][2], Pl[c][2]);
            split2(p[2 * c + 1][2], p[2 * c + 1][3], Ph[c][3], Pl[c][3]);
        }

#pragma unroll
        for (int kc = 0; kc < 4; ++kc) {
#pragma unroll
            for (int dp = 0; dp < 8; ++dp) {
                uint32_t ra = (uint32_t)((kc * 16 + rV) * 136 + dp * 16 + cV) * 2;
                uint32_t vh[4], vl[4];
                ldsm4t(vh, VHb + ra);
                ldsm4t(vl, VLb + ra);
                float* o0 = O[dp * 2];
                float* o1 = O[dp * 2 + 1];
                mma16816(o0, Ph[kc], vh);      mma16816(o1, Ph[kc], vh + 2);
                mma16816(o0, Ph[kc], vl);      mma16816(o1, Ph[kc], vl + 2);
                mma16816(o0, Pl[kc], vh);      mma16816(o1, Pl[kc], vh + 2);
            }
        }
        __syncthreads();
    }

    float inv0 = 1.f / l0, inv1 = 1.f / l1;
    size_t out0 = (qrow0 + w * 16 + g) * 128;
    size_t out1 = (qrow0 + w * 16 + g + 8) * 128;
#pragma unroll
    for (int nt = 0; nt < 16; ++nt) {
        int c0 = nt * 8 + 2 * t;
        uint32_t h, l;
        split2(O[nt][0] * inv0, O[nt][1] * inv0, h, l);
        *reinterpret_cast<uint32_t*>(g_xrh + out0 + c0) = h;
        *reinterpret_cast<uint32_t*>(g_xrl + out0 + c0) = l;
        split2(O[nt][2] * inv1, O[nt][3] * inv1, h, l);
        *reinterpret_cast<uint32_t*>(g_xrh + out1 + c0) = h;
        *reinterpret_cast<uint32_t*>(g_xrl + out1 + c0) = l;
    }
}

// ======================================================================
// BN finalize + epilogue
// ======================================================================
__global__ void k_stats()
{
    int f = threadIdx.x;
    float s = 0.f, q = 0.f;
    for (int b = 0; b < NQ / 64; ++b) {
        s += g_psum[b * 128 + f];
        q += g_psq [b * 128 + f];
    }
    float mean = s * (1.f / NQ);
    float var  = q * (1.f / NQ) - mean * mean;
    g_mean[f] = mean;
    g_rstd[f] = rsqrtf(var + BN_EPS);
}

__global__ void k_final(const float* __restrict__ gamma, const float* __restrict__ beta,
                        float* __restrict__ out)
{
    int idx = blockIdx.x * 256 + threadIdx.x;
    int f   = (idx & 31) * 4;
    float4 tv = *reinterpret_cast<const float4*>(g_t    + (size_t)idx * 4);
    float4 xd = *reinterpret_cast<const float4*>(g_xdec + (size_t)idx * 4);
    float4 r;
    r.x = xd.x + (tv.x - g_mean[f + 0]) * g_rstd[f + 0] * gamma[f + 0] + beta[f + 0];
    r.y = xd.y + (tv.y - g_mean[f + 1]) * g_rstd[f + 1] * gamma[f + 1] + beta[f + 1];
    r.z = xd.z + (tv.z - g_mean[f + 2]) * g_rstd[f + 2] * gamma[f + 2] + beta[f + 2];
    r.w = xd.w + (tv.w - g_mean[f + 3]) * g_rstd[f + 3] * gamma[f + 3] + beta[f + 3];
    *reinterpret_cast<float4*>(out + (size_t)idx * 4) = r;
}

// ======================================================================
extern "C" void kernel_launch(void* const* d_in, const int* in_sizes, int n_in,
                              void* d_out, int out_size)
{
    const float* xdec_f = (const float*)d_in[0];
    const float* xenc_f = (const float*)d_in[1];
    const int*   nbr    = (const int*)  d_in[2];
    const float* Wp1    = (const float*)d_in[3];
    const float* Wq     = (const float*)d_in[4];
    const float* Wk     = (const float*)d_in[5];
    const float* Wv     = (const float*)d_in[6];
    const float* Wt     = (const float*)d_in[7];
    const float* gamma  = (const float*)d_in[8];
    const float* beta   = (const float*)d_in[9];
    float* out = (float*)d_out;

    __nv_bfloat16 *p_xdh, *p_xdl, *p_xrh, *p_xrl;
    __nv_bfloat16 *p_wqh, *p_wql, *p_wth, *p_wtl;
    __nv_bfloat16 *p_qh, *p_ql;
    float *p_t;
    cudaGetSymbolAddress((void**)&p_xdh, g_xdh);  cudaGetSymbolAddress((void**)&p_xdl, g_xdl);
    cudaGetSymbolAddress((void**)&p_xrh, g_xrh);  cudaGetSymbolAddress((void**)&p_xrl, g_xrl);
    cudaGetSymbolAddress((void**)&p_wqh, g_wqh);  cudaGetSymbolAddress((void**)&p_wql, g_wql);
    cudaGetSymbolAddress((void**)&p_wth, g_wth);  cudaGetSymbolAddress((void**)&p_wtl, g_wtl);
    cudaGetSymbolAddress((void**)&p_qh,  g_qh);   cudaGetSymbolAddress((void**)&p_ql,  g_ql);
    cudaGetSymbolAddress((void**)&p_t,   g_t);

    cudaFuncSetAttribute(k_p1_mma,  cudaFuncAttributeMaxDynamicSharedMemorySize, 2 * GSTG);
    cudaFuncSetAttribute(k_projKV,  cudaFuncAttributeMaxDynamicSharedMemorySize, KVSMSZ);
    cudaFuncSetAttribute(k_proj<128, true,  false>, cudaFuncAttributeMaxDynamicSharedMemorySize, GSMSZ);
    cudaFuncSetAttribute(k_proj<128, false, true >, cudaFuncAttributeMaxDynamicSharedMemorySize, GSMSZ);
    cudaFuncSetAttribute(k_attn,    cudaFuncAttributeMaxDynamicSharedMemorySize, ASMSZ2);

    k_split7<<<SB6 / 1024, 256>>>(xdec_f, xenc_f, Wp1, Wk, Wv, Wq, Wt);
    k_p1_mma<<<NQ / 64, 256, 2 * GSTG>>>(nbr);
    k_projKV<<<NKV / 64, 256, KVSMSZ>>>();
    k_proj<128, true,  false><<<NQ / 64, 256, GSMSZ>>>(p_xdh, p_xdl, p_wqh, p_wql, p_qh, p_ql, nullptr);
    k_attn<<<dim3(NQB / 128, NBATCH), 256, ASMSZ2>>>();
    k_proj<128, false, true ><<<NQ / 64, 256, GSMSZ>>>(p_xrh, p_xrl, p_wth, p_wtl, nullptr, nullptr, p_t);
    k_stats<<<1, 128>>>();
    k_final<<<(NQ * NF / 4) / 256, 256>>>(gamma, beta, out);
}

// round 9
// speedup vs baseline: 4.5527x; 1.0666x over previous
#include <cuda_runtime.h>
#include <cuda_bf16.h>
#include <cuda_fp16.h>
#include <cstdint>

#define NQ      16384
#define NKV     32768
#define DEC     64
#define NF      128
#define NBATCH  8
#define NQB     2048
#define NKB     4096
#define BN_EPS  1e-4f

// ---------------- scratch (alloc-free: device globals) ----------------
__device__ float g_xdec[NQ * NF];
__device__ float g_t   [NQ * NF];
__device__ float g_psum[(NQ / 64) * NF];
__device__ float g_psq [(NQ / 64) * NF];
__device__ float g_mean[NF];
__device__ float g_rstd[NF];
__device__ __nv_bfloat16 g_dfh[NQ * DEC],  g_dfl[NQ * DEC];
__device__ __nv_bfloat16 g_eh [NKV * DEC], g_el [NKV * DEC];
__device__ __nv_bfloat16 g_wp1h[27 * 64 * 128], g_wp1l[27 * 64 * 128];
__device__ __nv_bfloat16 g_wkh[64 * 128],  g_wkl[64 * 128];
__device__ __nv_bfloat16 g_wvh[64 * 128],  g_wvl[64 * 128];
__device__ __nv_bfloat16 g_wqh[128 * 128], g_wql[128 * 128];
__device__ __nv_bfloat16 g_wth[128 * 128], g_wtl[128 * 128];
__device__ __nv_bfloat16 g_xdh[NQ * NF],  g_xdl[NQ * NF];
__device__ __nv_bfloat16 g_qh[NQ * NF],   g_ql[NQ * NF];
__device__ __nv_bfloat16 g_kh[NKV * NF],  g_kl[NKV * NF];
__device__ __half        g_vh[NKV * NF],  g_vl[NKV * NF];   // fp16 V hi/lo
__device__ __nv_bfloat16 g_xrh[NQ * NF],  g_xrl[NQ * NF];

// ---------------- helpers ----------------
__device__ __forceinline__ uint32_t packb(__nv_bfloat16 x, __nv_bfloat16 y) {
    __nv_bfloat162 v(x, y);
    return *reinterpret_cast<uint32_t*>(&v);
}
__device__ __forceinline__ void split2(float a, float b, uint32_t& hi, uint32_t& lo) {
    __nv_bfloat16 ah = __float2bfloat16(a);
    __nv_bfloat16 bh = __float2bfloat16(b);
    float ar = a - __bfloat162float(ah);
    float br = b - __bfloat162float(bh);
    hi = packb(ah, bh);
    lo = packb(__float2bfloat16(ar), __float2bfloat16(br));
}
__device__ __forceinline__ uint32_t packh(float a, float b) {
    __half2 h = __floats2half2_rn(a, b);
    return *reinterpret_cast<uint32_t*>(&h);
}
__device__ __forceinline__ void mma16816(float* d, const uint32_t* a, const uint32_t* b) {
    asm volatile("mma.sync.aligned.m16n8k16.row.col.f32.bf16.bf16.f32 "
                 "{%0,%1,%2,%3}, {%4,%5,%6,%7}, {%8,%9}, {%0,%1,%2,%3};"
                 : "+f"(d[0]), "+f"(d[1]), "+f"(d[2]), "+f"(d[3])
                 : "r"(a[0]), "r"(a[1]), "r"(a[2]), "r"(a[3]), "r"(b[0]), "r"(b[1]));
}
__device__ __forceinline__ void mma16816h(float* d, const uint32_t* a, const uint32_t* b) {
    asm volatile("mma.sync.aligned.m16n8k16.row.col.f32.f16.f16.f32 "
                 "{%0,%1,%2,%3}, {%4,%5,%6,%7}, {%8,%9}, {%0,%1,%2,%3};"
                 : "+f"(d[0]), "+f"(d[1]), "+f"(d[2]), "+f"(d[3])
                 : "r"(a[0]), "r"(a[1]), "r"(a[2]), "r"(a[3]), "r"(b[0]), "r"(b[1]));
}
__device__ __forceinline__ void ldsm4(uint32_t* r, uint32_t addr) {
    asm volatile("ldmatrix.sync.aligned.m8n8.x4.shared.b16 {%0,%1,%2,%3}, [%4];"
                 : "=r"(r[0]), "=r"(r[1]), "=r"(r[2]), "=r"(r[3]) : "r"(addr));
}
__device__ __forceinline__ void ldsm4t(uint32_t* r, uint32_t addr) {
    asm volatile("ldmatrix.sync.aligned.m8n8.x4.trans.shared.b16 {%0,%1,%2,%3}, [%4];"
                 : "=r"(r[0]), "=r"(r[1]), "=r"(r[2]), "=r"(r[3]) : "r"(addr));
}
__device__ __forceinline__ void cpa16(uint32_t dst, const void* src) {
    asm volatile("cp.async.cg.shared.global [%0], [%1], 16;" :: "r"(dst), "l"(src));
}
__device__ __forceinline__ void cpa_commit() {
    asm volatile("cp.async.commit_group;");
}

// ======================================================================
// Split-prep
// ======================================================================
#define SB0 (NQ * DEC)
#define SB1 (SB0 + NKV * DEC)
#define SB2 (SB1 + 27 * 64 * 128)
#define SB3 (SB2 + 64 * 128)
#define SB4 (SB3 + 64 * 128)
#define SB5 (SB4 + 128 * 128)
#define SB6 (SB5 + 128 * 128)

__device__ __forceinline__ void split4(float4 v, uint2& h, uint2& l) {
    uint32_t h0, l0, h1, l1;
    split2(v.x, v.y, h0, l0);
    split2(v.z, v.w, h1, l1);
    h = {h0, h1};
    l = {l0, l1};
}

__global__ void k_split7(const float* __restrict__ xdf, const float* __restrict__ xef,
                         const float* __restrict__ Wp1, const float* __restrict__ Wk,
                         const float* __restrict__ Wv,  const float* __restrict__ Wq,
                         const float* __restrict__ Wt)
{
    int e = (blockIdx.x * 256 + threadIdx.x) * 4;
    const float* src; __nv_bfloat16 *dh, *dl; int off;
    if      (e < SB0) { src = xdf; dh = g_dfh;  dl = g_dfl;  off = e; }
    else if (e < SB1) { src = xef; dh = g_eh;   dl = g_el;   off = e - SB0; }
    else if (e < SB2) { src = Wp1; dh = g_wp1h; dl = g_wp1l; off = e - SB1; }
    else if (e < SB3) { src = Wk;  dh = g_wkh;  dl = g_wkl;  off = e - SB2; }
    else if (e < SB4) { src = Wv;  dh = g_wvh;  dl = g_wvl;  off = e - SB3; }
    else if (e < SB5) { src = Wq;  dh = g_wqh;  dl = g_wql;  off = e - SB4; }
    else              { src = Wt;  dh = g_wth;  dl = g_wtl;  off = e - SB5; }
    float4 v = *reinterpret_cast<const float4*>(src + off);
    uint2 h, l;
    split4(v, h, l);
    *reinterpret_cast<uint2*>(dh + off) = h;
    *reinterpret_cast<uint2*>(dl + off) = l;
}

// ======================================================================
// Shared HMMA tile machinery (64x128 tile, 8 warps as 4 qw x 2 nw)
// ======================================================================
#define GOAH  0
#define GOAL  9216
#define GOBH  18432
#define GOBL  35840
#define GSTG  53248
#define GSMSZ (GSTG + 4096)

__device__ __forceinline__ void mma_tile64(uint32_t sbase,
                                           uint32_t bOffH, uint32_t bOffL,
                                           int qw, int nw, int lane,
                                           float acc[8][4])
{
    const int rA = lane & 15, cA = (lane >> 4) * 8;
    const int rV = ((lane >> 3) & 1) * 8 + (lane & 7);
    const int cV = ((lane >> 3) & 2) * 4;
#pragma unroll
    for (int kc = 0; kc < 4; ++kc) {
        uint32_t Aaddr = sbase + (uint32_t)((qw * 16 + rA) * 72 + kc * 16 + cA) * 2;
        uint32_t Ah4[4], Al4[4];
        ldsm4(Ah4, Aaddr + GOAH);
        ldsm4(Al4, Aaddr + GOAL);
#pragma unroll
        for (int nt2 = 0; nt2 < 4; ++nt2) {
            uint32_t ra = (uint32_t)((kc * 16 + rV) * 136 + nw * 64 + nt2 * 16 + cV) * 2;
            uint32_t Bh4[4], Bl4[4];
            ldsm4t(Bh4, sbase + bOffH + ra);
            ldsm4t(Bl4, sbase + bOffL + ra);
            float* a0 = acc[nt2 * 2];
            float* a1 = acc[nt2 * 2 + 1];
            mma16816(a0, Ah4, Bh4);  mma16816(a1, Ah4, Bh4 + 2);
            mma16816(a0, Ah4, Bl4);  mma16816(a1, Ah4, Bl4 + 2);
            mma16816(a0, Al4, Bh4);  mma16816(a1, Al4, Bh4 + 2);
        }
    }
}

// ======================================================================
// p1 gather-conv (unchanged winner)
// ======================================================================
__global__ __launch_bounds__(256) void k_p1_mma(const int* __restrict__ nbr)
{
    extern __shared__ char smr[];
    const uint32_t sbase = (uint32_t)__cvta_generic_to_shared(smr);
    const int tid = threadIdx.x;
    const int wid = tid >> 5, lane = tid & 31;
    const int qw = wid >> 1, nw = wid & 1;
    const int m0 = blockIdx.x * 64;

    float acc[8][4];
#pragma unroll
    for (int i = 0; i < 8; ++i)
#pragma unroll
        for (int j = 0; j < 4; ++j) acc[i][j] = 0.f;

    auto prefetch = [&](int k, int s) {
        uint32_t sb = sbase + s * GSTG;
#pragma unroll
        for (int i = 0; i < 2; ++i) {
            int idx = tid + i * 256;
            int r = idx >> 3, c = idx & 7;
            int gi = nbr[(m0 + r) * 27 + k];
            uint32_t so = (uint32_t)(r * 72 + c * 8) * 2;
            cpa16(sb + GOAH + so, g_dfh + (size_t)gi * DEC + c * 8);
            cpa16(sb + GOAL + so, g_dfl + (size_t)gi * DEC + c * 8);
        }
        const __nv_bfloat16* wh = g_wp1h + (size_t)k * 64 * 128;
        const __nv_bfloat16* wl = g_wp1l + (size_t)k * 64 * 128;
#pragma unroll
        for (int i = 0; i < 4; ++i) {
            int idx = tid + i * 256;
            int r = idx >> 4, c = idx & 15;
            uint32_t so = (uint32_t)(r * 136 + c * 8) * 2;
            cpa16(sb + GOBH + so, wh + r * 128 + c * 8);
            cpa16(sb + GOBL + so, wl + r * 128 + c * 8);
        }
        cpa_commit();
    };

    prefetch(0, 0);
    for (int k = 0; k < 27; ++k) {
        const int s = k & 1;
        if (k + 1 < 27) {
            prefetch(k + 1, s ^ 1);
            asm volatile("cp.async.wait_group 1;");
        } else {
            asm volatile("cp.async.wait_group 0;");
        }
        __syncthreads();
        mma_tile64(sbase + s * GSTG, GOBH, GOBL, qw, nw, lane, acc);
        __syncthreads();
    }

    const int g = lane >> 2, t = lane & 3;
    const int r0 = m0 + qw * 16 + g, r1 = r0 + 8;
#pragma unroll
    for (int nt = 0; nt < 8; ++nt) {
        int col = nw * 64 + nt * 8 + 2 * t;
        float2 v0 = {acc[nt][0], acc[nt][1]};
        float2 v1 = {acc[nt][2], acc[nt][3]};
        *reinterpret_cast<float2*>(g_xdec + (size_t)r0 * 128 + col) = v0;
        *reinterpret_cast<float2*>(g_xdec + (size_t)r1 * 128 + col) = v1;
        uint32_t h, l;
        split2(v0.x, v0.y, h, l);
        *reinterpret_cast<uint32_t*>(g_xdh + (size_t)r0 * 128 + col) = h;
        *reinterpret_cast<uint32_t*>(g_xdl + (size_t)r0 * 128 + col) = l;
        split2(v1.x, v1.y, h, l);
        *reinterpret_cast<uint32_t*>(g_xdh + (size_t)r1 * 128 + col) = h;
        *reinterpret_cast<uint32_t*>(g_xdl + (size_t)r1 * 128 + col) = l;
    }
}

// ======================================================================
// Fused K+V projection: K split-bf16, V split-fp16 (row-major)
// ======================================================================
#define KV_BKH 18432
#define KV_BKL (KV_BKH + 17408)
#define KV_BVH (KV_BKH + 34816)
#define KV_BVL (KV_BVH + 17408)
#define KVSMSZ (KV_BVH + 34816)

__global__ __launch_bounds__(256) void k_projKV()
{
    extern __shared__ char smr[];
    const uint32_t sbase = (uint32_t)__cvta_generic_to_shared(smr);
    const int tid = threadIdx.x;
    const int wid = tid >> 5, lane = tid & 31;
    const int qw = wid >> 1, nw = wid & 1;
    const int m0 = blockIdx.x * 64;

#pragma unroll
    for (int i = 0; i < 2; ++i) {
        int idx = tid + i * 256;
        int r = idx >> 3, c = idx & 7;
        size_t go = (size_t)(m0 + r) * DEC + c * 8;
        uint32_t so = (uint32_t)(r * 72 + c * 8) * 2;
        cpa16(sbase + GOAH + so, g_eh + go);
        cpa16(sbase + GOAL + so, g_el + go);
    }
#pragma unroll
    for (int i = 0; i < 4; ++i) {
        int idx = tid + i * 256;
        int r = idx >> 4, c = idx & 15;
        size_t go = (size_t)r * 128 + c * 8;
        uint32_t so = (uint32_t)(r * 136 + c * 8) * 2;
        cpa16(sbase + KV_BKH + so, g_wkh + go);
        cpa16(sbase + KV_BKL + so, g_wkl + go);
        cpa16(sbase + KV_BVH + so, g_wvh + go);
        cpa16(sbase + KV_BVL + so, g_wvl + go);
    }
    cpa_commit();
    asm volatile("cp.async.wait_group 0;");
    __syncthreads();

    float accK[8][4], accV[8][4];
#pragma unroll
    for (int i = 0; i < 8; ++i)
#pragma unroll
        for (int j = 0; j < 4; ++j) { accK[i][j] = 0.f; accV[i][j] = 0.f; }

    mma_tile64(sbase, KV_BKH, KV_BKL, qw, nw, lane, accK);
    mma_tile64(sbase, KV_BVH, KV_BVL, qw, nw, lane, accV);

    const int g = lane >> 2, t = lane & 3;
    const int r0 = m0 + qw * 16 + g, r1 = r0 + 8;
#pragma unroll
    for (int nt = 0; nt < 8; ++nt) {
        int col = nw * 64 + nt * 8 + 2 * t;
        uint32_t h, l;
        split2(accK[nt][0], accK[nt][1], h, l);
        *reinterpret_cast<uint32_t*>(g_kh + (size_t)r0 * 128 + col) = h;
        *reinterpret_cast<uint32_t*>(g_kl + (size_t)r0 * 128 + col) = l;
        split2(accK[nt][2], accK[nt][3], h, l);
        *reinterpret_cast<uint32_t*>(g_kh + (size_t)r1 * 128 + col) = h;
        *reinterpret_cast<uint32_t*>(g_kl + (size_t)r1 * 128 + col) = l;
        // V fp16 hi/lo
#pragma unroll
        for (int cc = 0; cc < 2; ++cc) {
            float v0 = accV[nt][cc];
            float v1 = accV[nt][2 + cc];
            __half h0 = __float2half_rn(v0);
            g_vh[(size_t)r0 * 128 + col + cc] = h0;
            g_vl[(size_t)r0 * 128 + col + cc] = __float2half_rn(v0 - __half2float(h0));
            __half h1 = __float2half_rn(v1);
            g_vh[(size_t)r1 * 128 + col + cc] = h1;
            g_vl[(size_t)r1 * 128 + col + cc] = __float2half_rn(v1 - __half2float(h1));
        }
    }
}

// ======================================================================
// Generic split-bf16 HMMA GEMM (+ split out / BN stats) — unchanged winner
// ======================================================================
template <int KA, bool SPLIT, bool STATS>
__global__ __launch_bounds__(256) void k_proj(const __nv_bfloat16* __restrict__ Ahg,
                                              const __nv_bfloat16* __restrict__ Alg,
                                              const __nv_bfloat16* __restrict__ Bhg,
                                              const __nv_bfloat16* __restrict__ Blg,
                                              __nv_bfloat16* __restrict__ Ch,
                                              __nv_bfloat16* __restrict__ Cl,
                                              float* __restrict__ Cf)
{
    extern __shared__ char smr[];
    const uint32_t sbase = (uint32_t)__cvta_generic_to_shared(smr);
    const int tid = threadIdx.x;
    const int wid = tid >> 5, lane = tid & 31;
    const int qw = wid >> 1, nw = wid & 1;
    const int m0 = blockIdx.x * 64;

    float acc[8][4];
#pragma unroll
    for (int i = 0; i < 8; ++i)
#pragma unroll
        for (int j = 0; j < 4; ++j) acc[i][j] = 0.f;

#pragma unroll
    for (int kb = 0; kb < KA / 64; ++kb) {
        __syncthreads();
#pragma unroll
        for (int i = 0; i < 2; ++i) {
            int idx = tid + i * 256;
            int r = idx >> 3, c = idx & 7;
            size_t go = (size_t)(m0 + r) * KA + kb * 64 + c * 8;
            uint32_t so = (uint32_t)(r * 72 + c * 8) * 2;
            cpa16(sbase + GOAH + so, Ahg + go);
            cpa16(sbase + GOAL + so, Alg + go);
        }
#pragma unroll
        for (int i = 0; i < 4; ++i) {
            int idx = tid + i * 256;
            int r = idx >> 4, c = idx & 15;
            size_t go = (size_t)(kb * 64 + r) * 128 + c * 8;
            uint32_t so = (uint32_t)(r * 136 + c * 8) * 2;
            cpa16(sbase + GOBH + so, Bhg + go);
            cpa16(sbase + GOBL + so, Blg + go);
        }
        cpa_commit();
        asm volatile("cp.async.wait_group 0;");
        __syncthreads();
        mma_tile64(sbase, GOBH, GOBL, qw, nw, lane, acc);
    }

    const int g = lane >> 2, t = lane & 3;
    const int r0 = m0 + qw * 16 + g, r1 = r0 + 8;
#pragma unroll
    for (int nt = 0; nt < 8; ++nt) {
        int col = nw * 64 + nt * 8 + 2 * t;
        if (SPLIT) {
            uint32_t h, l;
            split2(acc[nt][0], acc[nt][1], h, l);
            *reinterpret_cast<uint32_t*>(Ch + (size_t)r0 * 128 + col) = h;
            *reinterpret_cast<uint32_t*>(Cl + (size_t)r0 * 128 + col) = l;
            split2(acc[nt][2], acc[nt][3], h, l);
            *reinterpret_cast<uint32_t*>(Ch + (size_t)r1 * 128 + col) = h;
            *reinterpret_cast<uint32_t*>(Cl + (size_t)r1 * 128 + col) = l;
        } else {
            float2 v0 = {acc[nt][0], acc[nt][1]};
            float2 v1 = {acc[nt][2], acc[nt][3]};
            *reinterpret_cast<float2*>(Cf + (size_t)r0 * 128 + col) = v0;
            *reinterpret_cast<float2*>(Cf + (size_t)r1 * 128 + col) = v1;
        }
    }

    if (STATS) {
        float* sS = reinterpret_cast<float*>(smr);
        float* sQ = reinterpret_cast<float*>(smr + 2048);
        __syncthreads();
        float cs[8][2], cq[8][2];
#pragma unroll
        for (int nt = 0; nt < 8; ++nt) {
            cs[nt][0] = acc[nt][0] + acc[nt][2];
            cs[nt][1] = acc[nt][1] + acc[nt][3];
            cq[nt][0] = acc[nt][0] * acc[nt][0] + acc[nt][2] * acc[nt][2];
            cq[nt][1] = acc[nt][1] * acc[nt][1] + acc[nt][3] * acc[nt][3];
        }
#pragma unroll
        for (int off = 4; off < 32; off <<= 1) {
#pragma unroll
            for (int nt = 0; nt < 8; ++nt) {
                cs[nt][0] += __shfl_xor_sync(0xffffffffu, cs[nt][0], off);
                cs[nt][1] += __shfl_xor_sync(0xffffffffu, cs[nt][1], off);
                cq[nt][0] += __shfl_xor_sync(0xffffffffu, cq[nt][0], off);
                cq[nt][1] += __shfl_xor_sync(0xffffffffu, cq[nt][1], off);
            }
        }
        if (lane < 4) {
#pragma unroll
            for (int nt = 0; nt < 8; ++nt) {
                int col = nw * 64 + nt * 8 + 2 * lane;
                sS[qw * 128 + col]     = cs[nt][0];
                sS[qw * 128 + col + 1] = cs[nt][1];
                sQ[qw * 128 + col]     = cq[nt][0];
                sQ[qw * 128 + col + 1] = cq[nt][1];
            }
        }
        __syncthreads();
        if (tid < 128) {
            float s = sS[tid] + sS[128 + tid] + sS[256 + tid] + sS[384 + tid];
            float q = sQ[tid] + sQ[128 + tid] + sQ[256 + tid] + sQ[384 + tid];
            g_psum[blockIdx.x * 128 + tid] = s;
            g_psq [blockIdx.x * 128 + tid] = q;
        }
    }
}

// ======================================================================
// Flash attention: 128 q-rows/block, warp-private softmax, Q in regs,
// cp.async double-buffered K/V. kv tile 64 processed as two interleaved
// 32-halves; PV in fp16 2-term.
// ======================================================================
#define STG   17408
#define SSTAGE (4 * STG)
#define ASMSZ2 (2 * SSTAGE)

__global__ __launch_bounds__(256, 1) void k_attn()
{
    extern __shared__ char smr[];
    const uint32_t sbase = (uint32_t)__cvta_generic_to_shared(smr);

    const int tid  = threadIdx.x;
    const int w    = tid >> 5, lane = tid & 31;
    const int g    = lane >> 2, t = lane & 3;
    const int b    = blockIdx.y;
    const size_t qrow0 = (size_t)b * NQB + blockIdx.x * 128;

    const int rA = lane & 15;
    const int cA = (lane >> 4) * 8;
    const int rB = ((lane >> 3) & 2) * 4 + (lane & 7);
    const int cB = ((lane >> 3) & 1) * 8;
    const int rV = ((lane >> 3) & 1) * 8 + (lane & 7);
    const int cV = ((lane >> 3) & 2) * 4;

    // ---- stage Q, load register A-fragments ----
    uint32_t Qh[8][4], Ql[8][4];
    {
        const __nv_bfloat16* qh = g_qh + qrow0 * 128;
        const __nv_bfloat16* ql = g_ql + qrow0 * 128;
#pragma unroll
        for (int i = 0; i < 8; ++i) {
            int idx = tid + i * 256;
            int r = idx >> 4, c = idx & 15;
            uint32_t so = (uint32_t)(r * 136 + c * 8) * 2;
            cpa16(sbase + so,         qh + (size_t)r * 128 + c * 8);
            cpa16(sbase + 34816 + so, ql + (size_t)r * 128 + c * 8);
        }
        cpa_commit();
        asm volatile("cp.async.wait_group 0;");
        __syncthreads();
#pragma unroll
        for (int ch = 0; ch < 8; ++ch) {
            uint32_t Aaddr = sbase + (uint32_t)((w * 16 + rA) * 136 + ch * 16 + cA) * 2;
            ldsm4(Qh[ch], Aaddr);
            ldsm4(Ql[ch], Aaddr + 34816);
        }
        __syncthreads();
    }

    float O[16][4];
#pragma unroll
    for (int i = 0; i < 16; ++i)
#pragma unroll
        for (int j = 0; j < 4; ++j) O[i][j] = 0.f;
    float m0r = -1e30f, m1r = -1e30f, l0 = 0.f, l1 = 0.f;

    const size_t kvbase = (size_t)b * NKB * 128;
    auto prefetch = [&](int jt, int s) {
        size_t base = kvbase + (size_t)jt * 64 * 128;
        uint32_t sb = sbase + s * SSTAGE;
#pragma unroll
        for (int i = 0; i < 16; ++i) {
            int arr = i >> 2;
            int idx = tid + (i & 3) * 256;
            int r = idx >> 4, c = idx & 15;
            uint32_t so = sb + arr * STG + (uint32_t)(r * 136 + c * 8) * 2;
            size_t eo = base + (size_t)r * 128 + c * 8;
            const void* src;
            if      (arr == 0) src = g_kh + eo;
            else if (arr == 1) src = g_kl + eo;
            else if (arr == 2) src = g_vh + eo;
            else               src = g_vl + eo;
            cpa16(so, src);
        }
        cpa_commit();
    };

    prefetch(0, 0);

    const int NIT = NKB / 64;
    for (int jt = 0; jt < NIT; ++jt) {
        const int s = jt & 1;
        if (jt + 1 < NIT) {
            prefetch(jt + 1, s ^ 1);
            asm volatile("cp.async.wait_group 1;");
        } else {
            asm volatile("cp.async.wait_group 0;");
        }
        __syncthreads();

        const uint32_t KHb = sbase + s * SSTAGE;
        const uint32_t KLb = KHb + STG;
        const uint32_t VHb = KHb + 2 * STG;
        const uint32_t VLb = KHb + 3 * STG;

        // ---- S for BOTH halves (back-to-back MMA issue) ----
        float sA[8][4];
#pragma unroll
        for (int i = 0; i < 8; ++i)
#pragma unroll
            for (int j = 0; j < 4; ++j) sA[i][j] = 0.f;

#pragma unroll
        for (int half = 0; half < 2; ++half) {
#pragma unroll
            for (int ch = 0; ch < 8; ++ch) {
                uint32_t col = (uint32_t)(ch * 16 + cB) * 2;
#pragma unroll
                for (int r4h = 0; r4h < 2; ++r4h) {
                    int r4 = half * 2 + r4h;
                    uint32_t ra = (uint32_t)((r4 * 16 + rB) * 136) * 2 + col;
                    uint32_t bh[4], bl[4];
                    ldsm4(bh, KHb + ra);
                    ldsm4(bl, KLb + ra);
                    float* s0 = sA[r4 * 2];
                    float* s1 = sA[r4 * 2 + 1];
                    mma16816(s0, Qh[ch], bh);      mma16816(s1, Qh[ch], bh + 2);
                    mma16816(s0, Qh[ch], bl);      mma16816(s1, Qh[ch], bl + 2);
                    mma16816(s0, Ql[ch], bh);      mma16816(s1, Ql[ch], bh + 2);
                }
            }
        }

        // ---- per-half softmax + PV (softmax0 overlaps S1; softmax1 overlaps PV0) ----
#pragma unroll
        for (int half = 0; half < 2; ++half) {
            float (*sH)[4] = &sA[half * 4];

            float rm0 = sH[0][0], rm1 = sH[0][2];
#pragma unroll
            for (int nt = 0; nt < 4; ++nt) {
                rm0 = fmaxf(rm0, fmaxf(sH[nt][0], sH[nt][1]));
                rm1 = fmaxf(rm1, fmaxf(sH[nt][2], sH[nt][3]));
            }
            rm0 = fmaxf(rm0, __shfl_xor_sync(0xffffffffu, rm0, 1));
            rm0 = fmaxf(rm0, __shfl_xor_sync(0xffffffffu, rm0, 2));
            rm1 = fmaxf(rm1, __shfl_xor_sync(0xffffffffu, rm1, 1));
            rm1 = fmaxf(rm1, __shfl_xor_sync(0xffffffffu, rm1, 2));
            float mn0 = fmaxf(m0r, rm0);
            float mn1 = fmaxf(m1r, rm1);
            float sc0 = __expf(m0r - mn0);
            float sc1 = __expf(m1r - mn1);

            float p[4][4];
            float ls0 = 0.f, ls1 = 0.f;
#pragma unroll
            for (int nt = 0; nt < 4; ++nt) {
                p[nt][0] = __expf(sH[nt][0] - mn0);
                p[nt][1] = __expf(sH[nt][1] - mn0);
                p[nt][2] = __expf(sH[nt][2] - mn1);
                p[nt][3] = __expf(sH[nt][3] - mn1);
                ls0 += p[nt][0] + p[nt][1];
                ls1 += p[nt][2] + p[nt][3];
            }
            ls0 += __shfl_xor_sync(0xffffffffu, ls0, 1);
            ls0 += __shfl_xor_sync(0xffffffffu, ls0, 2);
            ls1 += __shfl_xor_sync(0xffffffffu, ls1, 1);
            ls1 += __shfl_xor_sync(0xffffffffu, ls1, 2);
            l0 = l0 * sc0 + ls0;
            l1 = l1 * sc1 + ls1;
            m0r = mn0; m1r = mn1;

#pragma unroll
            for (int nt = 0; nt < 16; ++nt) {
                O[nt][0] *= sc0; O[nt][1] *= sc0;
                O[nt][2] *= sc1; O[nt][3] *= sc1;
            }

            // P as plain fp16 A-fragments (2 k-chunks of 16 per half)
            uint32_t Ph[2][4];
#pragma unroll
            for (int c = 0; c < 2; ++c) {
                Ph[c][0] = packh(p[2 * c][0],     p[2 * c][1]);
                Ph[c][1] = packh(p[2 * c][2],     p[2 * c][3]);
                Ph[c][2] = packh(p[2 * c + 1][0], p[2 * c + 1][1]);
                Ph[c][3] = packh(p[2 * c + 1][2], p[2 * c + 1][3]);
            }

            // O += P(fp16) * (Vh + Vl)(fp16)
#pragma unroll
            for (int kcl = 0; kcl < 2; ++kcl) {
                int kc = half * 2 + kcl;
#pragma unroll
                for (int dp = 0; dp < 8; ++dp) {
                    uint32_t ra = (uint32_t)((kc * 16 + rV) * 136 + dp * 16 + cV) * 2;
                    uint32_t vh[4], vl[4];
                    ldsm4t(vh, VHb + ra);
                    ldsm4t(vl, VLb + ra);
                    float* o0 = O[dp * 2];
                    float* o1 = O[dp * 2 + 1];
                    mma16816h(o0, Ph[kcl], vh);    mma16816h(o1, Ph[kcl], vh + 2);
                    mma16816h(o0, Ph[kcl], vl);    mma16816h(o1, Ph[kcl], vl + 2);
                }
            }
        }
        __syncthreads();
    }

    // ---- epilogue: normalize, split, store ----
    float inv0 = 1.f / l0, inv1 = 1.f / l1;
    size_t out0 = (qrow0 + w * 16 + g) * 128;
    size_t out1 = (qrow0 + w * 16 + g + 8) * 128;
#pragma unroll
    for (int nt = 0; nt < 16; ++nt) {
        int c0 = nt * 8 + 2 * t;
        uint32_t h, l;
        split2(O[nt][0] * inv0, O[nt][1] * inv0, h, l);
        *reinterpret_cast<uint32_t*>(g_xrh + out0 + c0) = h;
        *reinterpret_cast<uint32_t*>(g_xrl + out0 + c0) = l;
        split2(O[nt][2] * inv1, O[nt][3] * inv1, h, l);
        *reinterpret_cast<uint32_t*>(g_xrh + out1 + c0) = h;
        *reinterpret_cast<uint32_t*>(g_xrl + out1 + c0) = l;
    }
}

// ======================================================================
// BN finalize + epilogue
// ======================================================================
__global__ void k_stats()
{
    int f = threadIdx.x;
    float s = 0.f, q = 0.f;
    for (int b = 0; b < NQ / 64; ++b) {
        s += g_psum[b * 128 + f];
        q += g_psq [b * 128 + f];
    }
    float mean = s * (1.f / NQ);
    float var  = q * (1.f / NQ) - mean * mean;
    g_mean[f] = mean;
    g_rstd[f] = rsqrtf(var + BN_EPS);
}

__global__ void k_final(const float* __restrict__ gamma, const float* __restrict__ beta,
                        float* __restrict__ out)
{
    int idx = blockIdx.x * 256 + threadIdx.x;
    int f   = (idx & 31) * 4;
    float4 tv = *reinterpret_cast<const float4*>(g_t    + (size_t)idx * 4);
    float4 xd = *reinterpret_cast<const float4*>(g_xdec + (size_t)idx * 4);
    float4 r;
    r.x = xd.x + (tv.x - g_mean[f + 0]) * g_rstd[f + 0] * gamma[f + 0] + beta[f + 0];
    r.y = xd.y + (tv.y - g_mean[f + 1]) * g_rstd[f + 1] * gamma[f + 1] + beta[f + 1];
    r.z = xd.z + (tv.z - g_mean[f + 2]) * g_rstd[f + 2] * gamma[f + 2] + beta[f + 2];
    r.w = xd.w + (tv.w - g_mean[f + 3]) * g_rstd[f + 3] * gamma[f + 3] + beta[f + 3];
    *reinterpret_cast<float4*>(out + (size_t)idx * 4) = r;
}

// ======================================================================
extern "C" void kernel_launch(void* const* d_in, const int* in_sizes, int n_in,
                              void* d_out, int out_size)
{
    const float* xdec_f = (const float*)d_in[0];
    const float* xenc_f = (const float*)d_in[1];
    const int*   nbr    = (const int*)  d_in[2];
    const float* Wp1    = (const float*)d_in[3];
    const float* Wq     = (const float*)d_in[4];
    const float* Wk     = (const float*)d_in[5];
    const float* Wv     = (const float*)d_in[6];
    const float* Wt     = (const float*)d_in[7];
    const float* gamma  = (const float*)d_in[8];
    const float* beta   = (const float*)d_in[9];
    float* out = (float*)d_out;

    __nv_bfloat16 *p_xdh, *p_xdl, *p_xrh, *p_xrl;
    __nv_bfloat16 *p_wqh, *p_wql, *p_wth, *p_wtl;
    __nv_bfloat16 *p_qh, *p_ql;
    float *p_t;
    cudaGetSymbolAddress((void**)&p_xdh, g_xdh);  cudaGetSymbolAddress((void**)&p_xdl, g_xdl);
    cudaGetSymbolAddress((void**)&p_xrh, g_xrh);  cudaGetSymbolAddress((void**)&p_xrl, g_xrl);
    cudaGetSymbolAddress((void**)&p_wqh, g_wqh);  cudaGetSymbolAddress((void**)&p_wql, g_wql);
    cudaGetSymbolAddress((void**)&p_wth, g_wth);  cudaGetSymbolAddress((void**)&p_wtl, g_wtl);
    cudaGetSymbolAddress((void**)&p_qh,  g_qh);   cudaGetSymbolAddress((void**)&p_ql,  g_ql);
    cudaGetSymbolAddress((void**)&p_t,   g_t);

    cudaFuncSetAttribute(k_p1_mma,  cudaFuncAttributeMaxDynamicSharedMemorySize, 2 * GSTG);
    cudaFuncSetAttribute(k_projKV,  cudaFuncAttributeMaxDynamicSharedMemorySize, KVSMSZ);
    cudaFuncSetAttribute(k_proj<128, true,  false>, cudaFuncAttributeMaxDynamicSharedMemorySize, GSMSZ);
    cudaFuncSetAttribute(k_proj<128, false, true >, cudaFuncAttributeMaxDynamicSharedMemorySize, GSMSZ);
    cudaFuncSetAttribute(k_attn,    cudaFuncAttributeMaxDynamicSharedMemorySize, ASMSZ2);

    k_split7<<<SB6 / 1024, 256>>>(xdec_f, xenc_f, Wp1, Wk, Wv, Wq, Wt);
    k_p1_mma<<<NQ / 64, 256, 2 * GSTG>>>(nbr);
    k_projKV<<<NKV / 64, 256, KVSMSZ>>>();
    k_proj<128, true,  false><<<NQ / 64, 256, GSMSZ>>>(p_xdh, p_xdl, p_wqh, p_wql, p_qh, p_ql, nullptr);
    k_attn<<<dim3(NQB / 128, NBATCH), 256, ASMSZ2>>>();
    k_proj<128, false, true ><<<NQ / 64, 256, GSMSZ>>>(p_xrh, p_xrl, p_wth, p_wtl, nullptr, nullptr, p_t);
    k_stats<<<1, 128>>>();
    k_final<<<(NQ * NF / 4) / 256, 256>>>(gamma, beta, out);
}